// round 1
// baseline (speedup 1.0000x reference)
#include <cuda_runtime.h>

// Problem constants
#define CC 64
#define BB 2
#define HH 128
#define WW 512
#define HW 65536          // HH*WW
#define PLANE 8388608L    // BB*CC*HW = one projection tensor, in floats
#define ATT_SCALE 0.125f  // 64^-0.5

// ---------------- scratch (static device allocations) ----------------
__device__ float g_T[4 * PLANE];                      // conv1x1 outputs (pre-dwconv)   134MB
__device__ float g_Q[4 * PLANE];                      // 0=Ql 1=Qr 2=Vl 3=Vr            134MB
__device__ float g_E[(long)BB * HH * WW * WW];        // exp(att) unnormalized          268MB
__device__ float g_F[2 * PLANE];                      // 0=F_r2l 1=F_l2r                 67MB

struct Ptrs4 { const float* p[4]; };

// =====================================================================
// K1: conv1x1 for all 4 projections.  T[p][b][o][pix] = sum_i W[o,i]*x[b][i][pix] + b[o]
// CTA: 256 threads, one (p,b,tile of 256 pixels). smem: X[64][256] + W[i][o] 64x64.
// Thread (og,lane): 8 out-channels (og*8+j) x 8 pixels (lane+32k). Coalesced STG.
// =====================================================================
extern "C" __global__ void __launch_bounds__(256)
k1_conv1x1(const float* __restrict__ xl, const float* __restrict__ xr,
           Ptrs4 w1, Ptrs4 b1)
{
    extern __shared__ float sm[];
    float* Xsm = sm;            // [i][px] 64*256
    float* Wsm = sm + 64 * 256; // [i][o]  64*64
    const int t    = threadIdx.x;
    const int tile = blockIdx.x;   // 0..255
    const int b    = blockIdx.y;
    const int p    = blockIdx.z;
    const float* __restrict__ x = (p & 1) ? xr : xl;
    const int base = tile * 256;

    // load X tile (coalesced), W transposed to [i][o] (STS conflict-free: addr==idx)
    #pragma unroll 4
    for (int idx = t; idx < 64 * 256; idx += 256) {
        int i = idx >> 8, px = idx & 255;
        Xsm[idx] = x[((long)(b * 64 + i)) * HW + base + px];
    }
    const float* __restrict__ w = w1.p[p];
    for (int idx = t; idx < 4096; idx += 256) {
        int o = idx & 63, i = idx >> 6;
        Wsm[idx] = w[o * 64 + i];   // Wsm[i*64+o] == Wsm[idx]
    }
    __syncthreads();

    const int og = t >> 5, lane = t & 31;
    float acc[8][8];
    #pragma unroll
    for (int j = 0; j < 8; j++)
        #pragma unroll
        for (int k = 0; k < 8; k++) acc[j][k] = 0.f;

    #pragma unroll 4
    for (int i = 0; i < 64; i++) {
        float wv[8], xv[8];
        #pragma unroll
        for (int j = 0; j < 8; j++) wv[j] = Wsm[i * 64 + og * 8 + j];
        #pragma unroll
        for (int k = 0; k < 8; k++) xv[k] = Xsm[i * 256 + lane + 32 * k];
        #pragma unroll
        for (int j = 0; j < 8; j++)
            #pragma unroll
            for (int k = 0; k < 8; k++) acc[j][k] += wv[j] * xv[k];
    }

    const float* __restrict__ bias = b1.p[p];
    #pragma unroll
    for (int j = 0; j < 8; j++) {
        int o = og * 8 + j;
        float bv = bias[o];
        long ob = ((long)p * BB + b) * 64L;
        ob = (ob + o) * HW + base;
        #pragma unroll
        for (int k = 0; k < 8; k++)
            g_T[ob + lane + 32 * k] = acc[j][k] + bv;
    }
}

// =====================================================================
// K2: depthwise 3x3, SAME padding. One thread = 4 consecutive w (float4 I/O).
// =====================================================================
__device__ __forceinline__ void dwrow(const float* __restrict__ row, int w0,
                                      float ka, float kb, float kc, float acc[4])
{
    float4 m = *(const float4*)(row + w0);
    float l = (w0 > 0)   ? row[w0 - 1] : 0.f;
    float r = (w0 < 508) ? row[w0 + 4] : 0.f;
    float col[6] = {l, m.x, m.y, m.z, m.w, r};
    #pragma unroll
    for (int k = 0; k < 4; k++)
        acc[k] += col[k] * ka + col[k + 1] * kb + col[k + 2] * kc;
}

extern "C" __global__ void __launch_bounds__(256)
k2_dwconv(Ptrs4 wd, Ptrs4 bd)
{
    long tid = (long)blockIdx.x * 256 + threadIdx.x;  // 0 .. 8388607
    int w0 = (int)(tid & 127) * 4;
    int h  = (int)(tid >> 7) & 127;
    int c  = (int)(tid >> 14) & 63;
    int b  = (int)(tid >> 20) & 1;
    int p  = (int)(tid >> 21);

    const float* __restrict__ W = wd.p[p] + c * 9;
    float k00 = W[0], k01 = W[1], k02 = W[2];
    float k10 = W[3], k11 = W[4], k12 = W[5];
    float k20 = W[6], k21 = W[7], k22 = W[8];

    const float* __restrict__ src = g_T + (((long)p * BB + b) * 64 + c) * HW + (long)h * WW;
    float acc[4] = {0.f, 0.f, 0.f, 0.f};
    if (h > 0)   dwrow(src - WW, w0, k00, k01, k02, acc);
    dwrow(src, w0, k10, k11, k12, acc);
    if (h < 127) dwrow(src + WW, w0, k20, k21, k22, acc);

    float bv = bd.p[p][c];
    float4 o;
    o.x = acc[0] + bv; o.y = acc[1] + bv; o.z = acc[2] + bv; o.w = acc[3] + bv;
    *(float4*)(g_Q + (((long)p * BB + b) * 64 + c) * HW + (long)h * WW + w0) = o;
}

// =====================================================================
// K3: per (b,h,wtile): E[64w][512v] = exp(SCALE * Ql^T Qr), store E,
//     rowsum over v, F_r2l[c, wtile] = (E @ Vr^T) / rowsum.
// =====================================================================
extern "C" __global__ void __launch_bounds__(256)
k3_r2l()
{
    extern __shared__ float sm[];
    float* Qlsm = sm;                 // [c][w] 64*64
    float* Qrsm = sm + 4096;          // [c][v]
    float* Vrsm = sm + 8192;          // [c][v]
    float* EsmT = sm + 12288;         // [v][w] padded 64*65
    float* rssm = sm + 12288 + 64 * 65;

    const int t  = threadIdx.x;
    const int wt = blockIdx.x, h = blockIdx.y, b = blockIdx.z;
    const int w0 = wt * 64;
    const int wg = t >> 5, lane = t & 31;

    const long qbase = ((long)b * 64) * HW + (long)h * WW;  // c stride = HW
    const float* __restrict__ Ql = g_Q + 0 * PLANE + qbase;
    const float* __restrict__ Qr = g_Q + 1 * PLANE + qbase;
    const float* __restrict__ Vr = g_Q + 3 * PLANE + qbase;
    float* __restrict__ Eg = g_E + (((long)b * HH + h) * WW) * WW;

    for (int idx = t; idx < 4096; idx += 256) {
        int c = idx >> 6, xw = idx & 63;
        Qlsm[idx] = Ql[(long)c * HW + w0 + xw];
    }

    float facc[8][2];
    float rs[8];
    #pragma unroll
    for (int j = 0; j < 8; j++) { facc[j][0] = 0.f; facc[j][1] = 0.f; rs[j] = 0.f; }

    for (int vt = 0; vt < 8; vt++) {
        const int v0 = vt * 64;
        __syncthreads();
        for (int idx = t; idx < 4096; idx += 256) {
            int c = idx >> 6, xv = idx & 63;
            Qrsm[idx] = Qr[(long)c * HW + v0 + xv];
            Vrsm[idx] = Vr[(long)c * HW + v0 + xv];
        }
        __syncthreads();

        // GEMM1: e[j][kv] = sum_c Ql[c][wg*8+j] * Qr[c][lane+32kv]
        float e[8][2];
        #pragma unroll
        for (int j = 0; j < 8; j++) { e[j][0] = 0.f; e[j][1] = 0.f; }
        #pragma unroll 4
        for (int c = 0; c < 64; c++) {
            float qr0 = Qrsm[c * 64 + lane];
            float qr1 = Qrsm[c * 64 + lane + 32];
            #pragma unroll
            for (int j = 0; j < 8; j++) {
                float ql = Qlsm[c * 64 + wg * 8 + j];
                e[j][0] += ql * qr0;
                e[j][1] += ql * qr1;
            }
        }
        // exp, rowsum, scatter to EsmT + global E
        #pragma unroll
        for (int j = 0; j < 8; j++) {
            int wloc = wg * 8 + j;
            #pragma unroll
            for (int kv = 0; kv < 2; kv++) {
                float ev = __expf(e[j][kv] * ATT_SCALE);
                rs[j] += ev;
                int vloc = lane + 32 * kv;
                EsmT[vloc * 65 + wloc] = ev;
                Eg[(long)(w0 + wloc) * WW + v0 + vloc] = ev;
            }
        }
        __syncthreads();

        // GEMM2: facc[j][kw] += sum_v Vr[wg*8+j][v] * E[lane+32kw][v]
        #pragma unroll 4
        for (int v = 0; v < 64; v++) {
            float et0 = EsmT[v * 65 + lane];
            float et1 = EsmT[v * 65 + lane + 32];
            #pragma unroll
            for (int j = 0; j < 8; j++) {
                float vr = Vrsm[(wg * 8 + j) * 64 + v];
                facc[j][0] += vr * et0;
                facc[j][1] += vr * et1;
            }
        }
    }

    // rowsum warp reduce (each lane summed a disjoint set of v for w = wg*8+j)
    #pragma unroll
    for (int j = 0; j < 8; j++) {
        float s = rs[j];
        #pragma unroll
        for (int off = 16; off; off >>= 1) s += __shfl_xor_sync(0xffffffffu, s, off);
        if (lane == 0) rssm[wg * 8 + j] = s;
    }
    __syncthreads();

    float inv0 = 1.f / rssm[lane];
    float inv1 = 1.f / rssm[lane + 32];
    float* __restrict__ F0 = g_F + ((long)b * 64) * HW + (long)h * WW;
    #pragma unroll
    for (int j = 0; j < 8; j++) {
        int c = wg * 8 + j;
        F0[(long)c * HW + w0 + lane]      = facc[j][0] * inv0;
        F0[(long)c * HW + w0 + lane + 32] = facc[j][1] * inv1;
    }
}

// =====================================================================
// K4: per (b,h,vtile): colsum over w, F_l2r[c, vtile] = (E^T-weighted Vl)/colsum
// =====================================================================
extern "C" __global__ void __launch_bounds__(256)
k4_l2r()
{
    __shared__ float Vlsm[4096];   // [c][w]
    __shared__ float Esm[4096];    // [w][v]
    __shared__ float cssm[64];

    const int t  = threadIdx.x;
    const int vt = blockIdx.x, h = blockIdx.y, b = blockIdx.z;
    const int v0 = vt * 64;
    const int cg = t >> 5, lane = t & 31;

    const float* __restrict__ Vl = g_Q + 2 * PLANE + ((long)b * 64) * HW + (long)h * WW;
    const float* __restrict__ Eg = g_E + (((long)b * HH + h) * WW) * WW;

    float facc[8][2];
    #pragma unroll
    for (int j = 0; j < 8; j++) { facc[j][0] = 0.f; facc[j][1] = 0.f; }
    float cs0 = 0.f, cs1 = 0.f;

    for (int wt = 0; wt < 8; wt++) {
        const int w0 = wt * 64;
        __syncthreads();
        for (int idx = t; idx < 4096; idx += 256) {
            int c = idx >> 6, xw = idx & 63;
            Vlsm[idx] = Vl[(long)c * HW + w0 + xw];
            Esm[idx]  = Eg[(long)(w0 + (idx >> 6)) * WW + v0 + (idx & 63)];
        }
        __syncthreads();

        #pragma unroll 4
        for (int w = 0; w < 64; w++) {
            float e0 = Esm[w * 64 + lane];
            float e1 = Esm[w * 64 + lane + 32];
            if (cg == 0) { cs0 += e0; cs1 += e1; }
            #pragma unroll
            for (int j = 0; j < 8; j++) {
                float vl = Vlsm[(cg * 8 + j) * 64 + w];
                facc[j][0] += vl * e0;
                facc[j][1] += vl * e1;
            }
        }
    }

    if (cg == 0) { cssm[lane] = cs0; cssm[lane + 32] = cs1; }
    __syncthreads();

    float inv0 = 1.f / cssm[lane];
    float inv1 = 1.f / cssm[lane + 32];
    float* __restrict__ F1 = g_F + PLANE + ((long)b * 64) * HW + (long)h * WW;
    #pragma unroll
    for (int j = 0; j < 8; j++) {
        int c = cg * 8 + j;
        F1[(long)c * HW + v0 + lane]      = facc[j][0] * inv0;
        F1[(long)c * HW + v0 + lane + 32] = facc[j][1] * inv1;
    }
}

// =====================================================================
// K5: out = x_l + x_r + conv1x1(F_r2l, lp3) + conv1x1(F_l2r, rp3)
// =====================================================================
extern "C" __global__ void __launch_bounds__(256)
k5_out(const float* __restrict__ xl, const float* __restrict__ xr,
       const float* __restrict__ wl3, const float* __restrict__ bl3,
       const float* __restrict__ wr3, const float* __restrict__ br3,
       float* __restrict__ out)
{
    extern __shared__ float sm[];
    float* F0sm = sm;               // [i][128]
    float* F1sm = sm + 8192;
    float* Wlsm = sm + 16384;       // [i][o]
    float* Wrsm = sm + 16384 + 4096;

    const int t = threadIdx.x;
    const int tile = blockIdx.x;    // 0..511
    const int b = blockIdx.y;
    const int base = tile * 128;

    for (int idx = t; idx < 8192; idx += 256) {
        int i = idx >> 7, px = idx & 127;
        long g = ((long)b * 64 + i) * HW + base + px;
        F0sm[idx] = g_F[g];
        F1sm[idx] = g_F[PLANE + g];
    }
    for (int idx = t; idx < 4096; idx += 256) {
        int o = idx & 63, i = idx >> 6;
        Wlsm[idx] = wl3[o * 64 + i];
        Wrsm[idx] = wr3[o * 64 + i];
    }
    __syncthreads();

    const int og = t >> 5, lane = t & 31;
    float acc[8][4];
    #pragma unroll
    for (int j = 0; j < 8; j++)
        #pragma unroll
        for (int k = 0; k < 4; k++) acc[j][k] = 0.f;

    #pragma unroll 4
    for (int i = 0; i < 64; i++) {
        float f0[4], f1[4], wv0[8], wv1[8];
        #pragma unroll
        for (int k = 0; k < 4; k++) {
            f0[k] = F0sm[i * 128 + lane + 32 * k];
            f1[k] = F1sm[i * 128 + lane + 32 * k];
        }
        #pragma unroll
        for (int j = 0; j < 8; j++) {
            wv0[j] = Wlsm[i * 64 + og * 8 + j];
            wv1[j] = Wrsm[i * 64 + og * 8 + j];
        }
        #pragma unroll
        for (int j = 0; j < 8; j++)
            #pragma unroll
            for (int k = 0; k < 4; k++)
                acc[j][k] += wv0[j] * f0[k] + wv1[j] * f1[k];
    }

    #pragma unroll
    for (int j = 0; j < 8; j++) {
        int o = og * 8 + j;
        float bv = bl3[o] + br3[o];
        long ob = ((long)b * 64 + o) * HW + base;
        #pragma unroll
        for (int k = 0; k < 4; k++) {
            int px = lane + 32 * k;
            out[ob + px] = acc[j][k] + bv + xl[ob + px] + xr[ob + px];
        }
    }
}

// =====================================================================
extern "C" void kernel_launch(void* const* d_in, const int* in_sizes, int n_in,
                              void* d_out, int out_size)
{
    const float* xl = (const float*)d_in[0];
    const float* xr = (const float*)d_in[1];
    Ptrs4 w1 = {{(const float*)d_in[2],  (const float*)d_in[6],
                 (const float*)d_in[10], (const float*)d_in[14]}};
    Ptrs4 b1 = {{(const float*)d_in[3],  (const float*)d_in[7],
                 (const float*)d_in[11], (const float*)d_in[15]}};
    Ptrs4 wd = {{(const float*)d_in[4],  (const float*)d_in[8],
                 (const float*)d_in[12], (const float*)d_in[16]}};
    Ptrs4 bd = {{(const float*)d_in[5],  (const float*)d_in[9],
                 (const float*)d_in[13], (const float*)d_in[17]}};
    const float* wl3 = (const float*)d_in[18];
    const float* bl3 = (const float*)d_in[19];
    const float* wr3 = (const float*)d_in[20];
    const float* br3 = (const float*)d_in[21];

    const int smem_k1 = (64 * 256 + 64 * 64) * 4;                 // 81920
    const int smem_k3 = (4096 * 3 + 64 * 65 + 64) * 4;            // 66048
    const int smem_k5 = (8192 * 2 + 4096 * 2) * 4;                // 98304
    cudaFuncSetAttribute(k1_conv1x1, cudaFuncAttributeMaxDynamicSharedMemorySize, smem_k1);
    cudaFuncSetAttribute(k3_r2l,     cudaFuncAttributeMaxDynamicSharedMemorySize, smem_k3);
    cudaFuncSetAttribute(k5_out,     cudaFuncAttributeMaxDynamicSharedMemorySize, smem_k5);

    k1_conv1x1<<<dim3(256, 2, 4), 256, smem_k1>>>(xl, xr, w1, b1);
    k2_dwconv<<<32768, 256>>>(wd, bd);
    k3_r2l<<<dim3(8, 128, 2), 256, smem_k3>>>();
    k4_l2r<<<dim3(8, 128, 2), 256>>>();
    k5_out<<<dim3(512, 2), 256, smem_k5>>>(xl, xr, wl3, bl3, wr3, br3, (float*)d_out);
}

// round 2
// speedup vs baseline: 1.0064x; 1.0064x over previous
#include <cuda_runtime.h>

// Problem constants
#define CC 64
#define BB 2
#define HH 128
#define WW 512
#define HW 65536          // HH*WW
#define PLANE 8388608L    // BB*CC*HW = one projection tensor, in floats
#define ATT_SCALE 0.125f  // 64^-0.5

// ---------------- scratch (static device allocations) ----------------
__device__ float g_T[4 * PLANE];                      // conv1x1 outputs (pre-dwconv)   134MB
__device__ float g_Q[4 * PLANE];                      // 0=Ql 1=Qr 2=Vl 3=Vr            134MB
__device__ float g_E[(long)BB * HH * WW * WW];        // exp(att) unnormalized          268MB
__device__ float g_F[2 * PLANE];                      // 0=F_r2l 1=F_l2r                 67MB

struct Ptrs4 { const float* p[4]; };

// =====================================================================
// K1: conv1x1 for all 4 projections.  T[p][b][o][pix] = sum_i W[o,i]*x[b][i][pix] + b[o]
// CTA: 256 threads, one (p,b,tile of 256 pixels). smem: X[64][256] + W[i][o] 64x64.
// Thread (og,lane): 8 out-channels (og*8+j) x 8 pixels (lane+32k). Coalesced STG.
// =====================================================================
extern "C" __global__ void __launch_bounds__(256)
k1_conv1x1(const float* __restrict__ xl, const float* __restrict__ xr,
           Ptrs4 w1, Ptrs4 b1)
{
    extern __shared__ float sm[];
    float* Xsm = sm;            // [i][px] 64*256
    float* Wsm = sm + 64 * 256; // [i][o]  64*64
    const int t    = threadIdx.x;
    const int tile = blockIdx.x;   // 0..255
    const int b    = blockIdx.y;
    const int p    = blockIdx.z;
    const float* __restrict__ x = (p & 1) ? xr : xl;
    const int base = tile * 256;

    // load X tile (coalesced), W transposed to [i][o] (STS conflict-free: addr==idx)
    #pragma unroll 4
    for (int idx = t; idx < 64 * 256; idx += 256) {
        int i = idx >> 8, px = idx & 255;
        Xsm[idx] = x[((long)(b * 64 + i)) * HW + base + px];
    }
    const float* __restrict__ w = w1.p[p];
    for (int idx = t; idx < 4096; idx += 256) {
        int o = idx & 63, i = idx >> 6;
        Wsm[idx] = w[o * 64 + i];   // Wsm[i*64+o] == Wsm[idx]
    }
    __syncthreads();

    const int og = t >> 5, lane = t & 31;
    float acc[8][8];
    #pragma unroll
    for (int j = 0; j < 8; j++)
        #pragma unroll
        for (int k = 0; k < 8; k++) acc[j][k] = 0.f;

    #pragma unroll 4
    for (int i = 0; i < 64; i++) {
        float wv[8], xv[8];
        #pragma unroll
        for (int j = 0; j < 8; j++) wv[j] = Wsm[i * 64 + og * 8 + j];
        #pragma unroll
        for (int k = 0; k < 8; k++) xv[k] = Xsm[i * 256 + lane + 32 * k];
        #pragma unroll
        for (int j = 0; j < 8; j++)
            #pragma unroll
            for (int k = 0; k < 8; k++) acc[j][k] += wv[j] * xv[k];
    }

    const float* __restrict__ bias = b1.p[p];
    #pragma unroll
    for (int j = 0; j < 8; j++) {
        int o = og * 8 + j;
        float bv = bias[o];
        long ob = ((long)p * BB + b) * 64L;
        ob = (ob + o) * HW + base;
        #pragma unroll
        for (int k = 0; k < 8; k++)
            g_T[ob + lane + 32 * k] = acc[j][k] + bv;
    }
}

// =====================================================================
// K2: depthwise 3x3, SAME padding. One thread = 4 consecutive w (float4 I/O).
// =====================================================================
__device__ __forceinline__ void dwrow(const float* __restrict__ row, int w0,
                                      float ka, float kb, float kc, float acc[4])
{
    float4 m = *(const float4*)(row + w0);
    float l = (w0 > 0)   ? row[w0 - 1] : 0.f;
    float r = (w0 < 508) ? row[w0 + 4] : 0.f;
    float col[6] = {l, m.x, m.y, m.z, m.w, r};
    #pragma unroll
    for (int k = 0; k < 4; k++)
        acc[k] += col[k] * ka + col[k + 1] * kb + col[k + 2] * kc;
}

extern "C" __global__ void __launch_bounds__(256)
k2_dwconv(Ptrs4 wd, Ptrs4 bd)
{
    long tid = (long)blockIdx.x * 256 + threadIdx.x;  // 0 .. 8388607
    int w0 = (int)(tid & 127) * 4;
    int h  = (int)(tid >> 7) & 127;
    int c  = (int)(tid >> 14) & 63;
    int b  = (int)(tid >> 20) & 1;
    int p  = (int)(tid >> 21);

    const float* __restrict__ W = wd.p[p] + c * 9;
    float k00 = W[0], k01 = W[1], k02 = W[2];
    float k10 = W[3], k11 = W[4], k12 = W[5];
    float k20 = W[6], k21 = W[7], k22 = W[8];

    const float* __restrict__ src = g_T + (((long)p * BB + b) * 64 + c) * HW + (long)h * WW;
    float acc[4] = {0.f, 0.f, 0.f, 0.f};
    if (h > 0)   dwrow(src - WW, w0, k00, k01, k02, acc);
    dwrow(src, w0, k10, k11, k12, acc);
    if (h < 127) dwrow(src + WW, w0, k20, k21, k22, acc);

    float bv = bd.p[p][c];
    float4 o;
    o.x = acc[0] + bv; o.y = acc[1] + bv; o.z = acc[2] + bv; o.w = acc[3] + bv;
    *(float4*)(g_Q + (((long)p * BB + b) * 64 + c) * HW + (long)h * WW + w0) = o;
}

// =====================================================================
// K3: per (b,h,wtile): E[64w][512v] = exp(SCALE * Ql^T Qr), store E,
//     rowsum over v, F_r2l[c, wtile] = (E @ Vr^T) / rowsum.
// =====================================================================
extern "C" __global__ void __launch_bounds__(256)
k3_r2l()
{
    extern __shared__ float sm[];
    float* Qlsm = sm;                 // [c][w] 64*64
    float* Qrsm = sm + 4096;          // [c][v]
    float* Vrsm = sm + 8192;          // [c][v]
    float* EsmT = sm + 12288;         // [v][w] padded 64*65
    float* rssm = sm + 12288 + 64 * 65;

    const int t  = threadIdx.x;
    const int wt = blockIdx.x, h = blockIdx.y, b = blockIdx.z;
    const int w0 = wt * 64;
    const int wg = t >> 5, lane = t & 31;

    const long qbase = ((long)b * 64) * HW + (long)h * WW;  // c stride = HW
    const float* __restrict__ Ql = g_Q + 0 * PLANE + qbase;
    const float* __restrict__ Qr = g_Q + 1 * PLANE + qbase;
    const float* __restrict__ Vr = g_Q + 3 * PLANE + qbase;
    float* __restrict__ Eg = g_E + (((long)b * HH + h) * WW) * WW;

    for (int idx = t; idx < 4096; idx += 256) {
        int c = idx >> 6, xw = idx & 63;
        Qlsm[idx] = Ql[(long)c * HW + w0 + xw];
    }

    float facc[8][2];
    float rs[8];
    #pragma unroll
    for (int j = 0; j < 8; j++) { facc[j][0] = 0.f; facc[j][1] = 0.f; rs[j] = 0.f; }

    for (int vt = 0; vt < 8; vt++) {
        const int v0 = vt * 64;
        __syncthreads();
        for (int idx = t; idx < 4096; idx += 256) {
            int c = idx >> 6, xv = idx & 63;
            Qrsm[idx] = Qr[(long)c * HW + v0 + xv];
            Vrsm[idx] = Vr[(long)c * HW + v0 + xv];
        }
        __syncthreads();

        // GEMM1: e[j][kv] = sum_c Ql[c][wg*8+j] * Qr[c][lane+32kv]
        float e[8][2];
        #pragma unroll
        for (int j = 0; j < 8; j++) { e[j][0] = 0.f; e[j][1] = 0.f; }
        #pragma unroll 4
        for (int c = 0; c < 64; c++) {
            float qr0 = Qrsm[c * 64 + lane];
            float qr1 = Qrsm[c * 64 + lane + 32];
            #pragma unroll
            for (int j = 0; j < 8; j++) {
                float ql = Qlsm[c * 64 + wg * 8 + j];
                e[j][0] += ql * qr0;
                e[j][1] += ql * qr1;
            }
        }
        // exp, rowsum, scatter to EsmT + global E
        #pragma unroll
        for (int j = 0; j < 8; j++) {
            int wloc = wg * 8 + j;
            #pragma unroll
            for (int kv = 0; kv < 2; kv++) {
                float ev = __expf(e[j][kv] * ATT_SCALE);
                rs[j] += ev;
                int vloc = lane + 32 * kv;
                EsmT[vloc * 65 + wloc] = ev;
                Eg[(long)(w0 + wloc) * WW + v0 + vloc] = ev;
            }
        }
        __syncthreads();

        // GEMM2: facc[j][kw] += sum_v Vr[wg*8+j][v] * E[lane+32kw][v]
        #pragma unroll 4
        for (int v = 0; v < 64; v++) {
            float et0 = EsmT[v * 65 + lane];
            float et1 = EsmT[v * 65 + lane + 32];
            #pragma unroll
            for (int j = 0; j < 8; j++) {
                float vr = Vrsm[(wg * 8 + j) * 64 + v];
                facc[j][0] += vr * et0;
                facc[j][1] += vr * et1;
            }
        }
    }

    // rowsum warp reduce (each lane summed a disjoint set of v for w = wg*8+j)
    #pragma unroll
    for (int j = 0; j < 8; j++) {
        float s = rs[j];
        #pragma unroll
        for (int off = 16; off; off >>= 1) s += __shfl_xor_sync(0xffffffffu, s, off);
        if (lane == 0) rssm[wg * 8 + j] = s;
    }
    __syncthreads();

    float inv0 = 1.f / rssm[lane];
    float inv1 = 1.f / rssm[lane + 32];
    float* __restrict__ F0 = g_F + ((long)b * 64) * HW + (long)h * WW;
    #pragma unroll
    for (int j = 0; j < 8; j++) {
        int c = wg * 8 + j;
        F0[(long)c * HW + w0 + lane]      = facc[j][0] * inv0;
        F0[(long)c * HW + w0 + lane + 32] = facc[j][1] * inv1;
    }
}

// =====================================================================
// K4: per (b,h,vtile): colsum over w, F_l2r[c, vtile] = (E^T-weighted Vl)/colsum
// =====================================================================
extern "C" __global__ void __launch_bounds__(256)
k4_l2r()
{
    __shared__ float Vlsm[4096];   // [c][w]
    __shared__ float Esm[4096];    // [w][v]
    __shared__ float cssm[64];

    const int t  = threadIdx.x;
    const int vt = blockIdx.x, h = blockIdx.y, b = blockIdx.z;
    const int v0 = vt * 64;
    const int cg = t >> 5, lane = t & 31;

    const float* __restrict__ Vl = g_Q + 2 * PLANE + ((long)b * 64) * HW + (long)h * WW;
    const float* __restrict__ Eg = g_E + (((long)b * HH + h) * WW) * WW;

    float facc[8][2];
    #pragma unroll
    for (int j = 0; j < 8; j++) { facc[j][0] = 0.f; facc[j][1] = 0.f; }
    float cs0 = 0.f, cs1 = 0.f;

    for (int wt = 0; wt < 8; wt++) {
        const int w0 = wt * 64;
        __syncthreads();
        for (int idx = t; idx < 4096; idx += 256) {
            int c = idx >> 6, xw = idx & 63;
            Vlsm[idx] = Vl[(long)c * HW + w0 + xw];
            Esm[idx]  = Eg[(long)(w0 + (idx >> 6)) * WW + v0 + (idx & 63)];
        }
        __syncthreads();

        #pragma unroll 4
        for (int w = 0; w < 64; w++) {
            float e0 = Esm[w * 64 + lane];
            float e1 = Esm[w * 64 + lane + 32];
            if (cg == 0) { cs0 += e0; cs1 += e1; }
            #pragma unroll
            for (int j = 0; j < 8; j++) {
                float vl = Vlsm[(cg * 8 + j) * 64 + w];
                facc[j][0] += vl * e0;
                facc[j][1] += vl * e1;
            }
        }
    }

    if (cg == 0) { cssm[lane] = cs0; cssm[lane + 32] = cs1; }
    __syncthreads();

    float inv0 = 1.f / cssm[lane];
    float inv1 = 1.f / cssm[lane + 32];
    float* __restrict__ F1 = g_F + PLANE + ((long)b * 64) * HW + (long)h * WW;
    #pragma unroll
    for (int j = 0; j < 8; j++) {
        int c = cg * 8 + j;
        F1[(long)c * HW + v0 + lane]      = facc[j][0] * inv0;
        F1[(long)c * HW + v0 + lane + 32] = facc[j][1] * inv1;
    }
}

// =====================================================================
// K5: out = x_l + x_r + conv1x1(F_r2l, lp3) + conv1x1(F_l2r, rp3)
// =====================================================================
extern "C" __global__ void __launch_bounds__(256)
k5_out(const float* __restrict__ xl, const float* __restrict__ xr,
       const float* __restrict__ wl3, const float* __restrict__ bl3,
       const float* __restrict__ wr3, const float* __restrict__ br3,
       float* __restrict__ out)
{
    extern __shared__ float sm[];
    float* F0sm = sm;               // [i][128]
    float* F1sm = sm + 8192;
    float* Wlsm = sm + 16384;       // [i][o]
    float* Wrsm = sm + 16384 + 4096;

    const int t = threadIdx.x;
    const int tile = blockIdx.x;    // 0..511
    const int b = blockIdx.y;
    const int base = tile * 128;

    for (int idx = t; idx < 8192; idx += 256) {
        int i = idx >> 7, px = idx & 127;
        long g = ((long)b * 64 + i) * HW + base + px;
        F0sm[idx] = g_F[g];
        F1sm[idx] = g_F[PLANE + g];
    }
    for (int idx = t; idx < 4096; idx += 256) {
        int o = idx & 63, i = idx >> 6;
        Wlsm[idx] = wl3[o * 64 + i];
        Wrsm[idx] = wr3[o * 64 + i];
    }
    __syncthreads();

    const int og = t >> 5, lane = t & 31;
    float acc[8][4];
    #pragma unroll
    for (int j = 0; j < 8; j++)
        #pragma unroll
        for (int k = 0; k < 4; k++) acc[j][k] = 0.f;

    #pragma unroll 4
    for (int i = 0; i < 64; i++) {
        float f0[4], f1[4], wv0[8], wv1[8];
        #pragma unroll
        for (int k = 0; k < 4; k++) {
            f0[k] = F0sm[i * 128 + lane + 32 * k];
            f1[k] = F1sm[i * 128 + lane + 32 * k];
        }
        #pragma unroll
        for (int j = 0; j < 8; j++) {
            wv0[j] = Wlsm[i * 64 + og * 8 + j];
            wv1[j] = Wrsm[i * 64 + og * 8 + j];
        }
        #pragma unroll
        for (int j = 0; j < 8; j++)
            #pragma unroll
            for (int k = 0; k < 4; k++)
                acc[j][k] += wv0[j] * f0[k] + wv1[j] * f1[k];
    }

    #pragma unroll
    for (int j = 0; j < 8; j++) {
        int o = og * 8 + j;
        float bv = bl3[o] + br3[o];
        long ob = ((long)b * 64 + o) * HW + base;
        #pragma unroll
        for (int k = 0; k < 4; k++) {
            int px = lane + 32 * k;
            out[ob + px] = acc[j][k] + bv + xl[ob + px] + xr[ob + px];
        }
    }
}

// =====================================================================
extern "C" void kernel_launch(void* const* d_in, const int* in_sizes, int n_in,
                              void* d_out, int out_size)
{
    const float* xl = (const float*)d_in[0];
    const float* xr = (const float*)d_in[1];
    Ptrs4 w1 = {{(const float*)d_in[2],  (const float*)d_in[6],
                 (const float*)d_in[10], (const float*)d_in[14]}};
    Ptrs4 b1 = {{(const float*)d_in[3],  (const float*)d_in[7],
                 (const float*)d_in[11], (const float*)d_in[15]}};
    Ptrs4 wd = {{(const float*)d_in[4],  (const float*)d_in[8],
                 (const float*)d_in[12], (const float*)d_in[16]}};
    Ptrs4 bd = {{(const float*)d_in[5],  (const float*)d_in[9],
                 (const float*)d_in[13], (const float*)d_in[17]}};
    const float* wl3 = (const float*)d_in[18];
    const float* bl3 = (const float*)d_in[19];
    const float* wr3 = (const float*)d_in[20];
    const float* br3 = (const float*)d_in[21];

    const int smem_k1 = (64 * 256 + 64 * 64) * 4;                 // 81920
    const int smem_k3 = (4096 * 3 + 64 * 65 + 64) * 4;            // 66048
    const int smem_k5 = (8192 * 2 + 4096 * 2) * 4;                // 98304
    cudaFuncSetAttribute(k1_conv1x1, cudaFuncAttributeMaxDynamicSharedMemorySize, smem_k1);
    cudaFuncSetAttribute(k3_r2l,     cudaFuncAttributeMaxDynamicSharedMemorySize, smem_k3);
    cudaFuncSetAttribute(k5_out,     cudaFuncAttributeMaxDynamicSharedMemorySize, smem_k5);

    k1_conv1x1<<<dim3(256, 2, 4), 256, smem_k1>>>(xl, xr, w1, b1);
    k2_dwconv<<<32768, 256>>>(wd, bd);
    k3_r2l<<<dim3(8, 128, 2), 256, smem_k3>>>();
    k4_l2r<<<dim3(8, 128, 2), 256>>>();
    k5_out<<<dim3(512, 2), 256, smem_k5>>>(xl, xr, wl3, bl3, wr3, br3, (float*)d_out);
}

// round 4
// speedup vs baseline: 1.8109x; 1.7993x over previous
#include <cuda_runtime.h>
#include <cuda_bf16.h>

#define CC 64
#define BB 2
#define HH 128
#define WW 512
#define HW 65536
#define PLANE 8388608L
#define ATT_SCALE 0.125f

__device__ float         g_T[4 * PLANE];    // conv1x1 outputs fp32
__device__ __nv_bfloat16 g_Qn[4 * PLANE];   // dwconv out, natural [c][w] bf16
__device__ __nv_bfloat16 g_QT[2 * PLANE];   // Ql,Qr transposed [b][h][pix][c] bf16
__device__ float         g_F[2 * PLANE];    // F_r2l, F_l2r fp32

struct Ptrs4 { const float* p[4]; };

// ===================== helpers =====================
__device__ __forceinline__ unsigned smem_u32(const void* p) {
    unsigned a;
    asm("{ .reg .u64 t; cvta.to.shared.u64 t, %1; cvt.u32.u64 %0, t; }" : "=r"(a) : "l"(p));
    return a;
}
__device__ __forceinline__ void ldsm4(unsigned a, unsigned r[4]) {
    asm volatile("ldmatrix.sync.aligned.m8n8.x4.shared.b16 {%0,%1,%2,%3}, [%4];"
        : "=r"(r[0]), "=r"(r[1]), "=r"(r[2]), "=r"(r[3]) : "r"(a));
}
__device__ __forceinline__ void mma_bf16(float c[4], const unsigned a[4], const unsigned b[2]) {
    asm volatile("mma.sync.aligned.m16n8k16.row.col.f32.bf16.bf16.f32 "
        "{%0,%1,%2,%3}, {%4,%5,%6,%7}, {%8,%9}, {%0,%1,%2,%3};"
        : "+f"(c[0]), "+f"(c[1]), "+f"(c[2]), "+f"(c[3])
        : "r"(a[0]), "r"(a[1]), "r"(a[2]), "r"(a[3]), "r"(b[0]), "r"(b[1]));
}
#define SWZ(o) ((o) ^ (((o) >> 3) & 0x70))

// =====================================================================
// K1: conv1x1 for all 4 projections (fp32 register-tiled GEMM)
// =====================================================================
extern "C" __global__ void __launch_bounds__(256)
k1_conv1x1(const float* __restrict__ xl, const float* __restrict__ xr,
           Ptrs4 w1, Ptrs4 b1)
{
    extern __shared__ float sm[];
    float* Xsm = sm;            // [i][px] 64*256
    float* Wsm = sm + 64 * 256; // [i][o]
    const int t = threadIdx.x, tile = blockIdx.x, b = blockIdx.y, p = blockIdx.z;
    const float* __restrict__ x = (p & 1) ? xr : xl;
    const int base = tile * 256;

    #pragma unroll 4
    for (int idx = t; idx < 64 * 256; idx += 256) {
        int i = idx >> 8, px = idx & 255;
        Xsm[idx] = x[((long)(b * 64 + i)) * HW + base + px];
    }
    const float* __restrict__ w = w1.p[p];
    for (int idx = t; idx < 4096; idx += 256) {
        int o = idx & 63, i = idx >> 6;
        Wsm[idx] = w[o * 64 + i];
    }
    __syncthreads();

    const int og = t >> 5, lane = t & 31;
    float acc[8][8];
    #pragma unroll
    for (int j = 0; j < 8; j++)
        #pragma unroll
        for (int k = 0; k < 8; k++) acc[j][k] = 0.f;

    #pragma unroll 4
    for (int i = 0; i < 64; i++) {
        float wv[8], xv[8];
        #pragma unroll
        for (int j = 0; j < 8; j++) wv[j] = Wsm[i * 64 + og * 8 + j];
        #pragma unroll
        for (int k = 0; k < 8; k++) xv[k] = Xsm[i * 256 + lane + 32 * k];
        #pragma unroll
        for (int j = 0; j < 8; j++)
            #pragma unroll
            for (int k = 0; k < 8; k++) acc[j][k] += wv[j] * xv[k];
    }

    const float* __restrict__ bias = b1.p[p];
    #pragma unroll
    for (int j = 0; j < 8; j++) {
        int o = og * 8 + j;
        float bv = bias[o];
        long ob = (((long)p * BB + b) * 64 + o) * HW + base;
        #pragma unroll
        for (int k = 0; k < 8; k++)
            g_T[ob + lane + 32 * k] = acc[j][k] + bv;
    }
}

// =====================================================================
// K2: depthwise 3x3 -> bf16 natural layout
// =====================================================================
__device__ __forceinline__ void dwrow(const float* __restrict__ row, int w0,
                                      float ka, float kb, float kc, float acc[4])
{
    float4 m = *(const float4*)(row + w0);
    float l = (w0 > 0)   ? row[w0 - 1] : 0.f;
    float r = (w0 < 508) ? row[w0 + 4] : 0.f;
    float col[6] = {l, m.x, m.y, m.z, m.w, r};
    #pragma unroll
    for (int k = 0; k < 4; k++)
        acc[k] += col[k] * ka + col[k + 1] * kb + col[k + 2] * kc;
}

extern "C" __global__ void __launch_bounds__(256)
k2_dwconv(Ptrs4 wd, Ptrs4 bd)
{
    long tid = (long)blockIdx.x * 256 + threadIdx.x;
    int w0 = (int)(tid & 127) * 4;
    int h  = (int)(tid >> 7) & 127;
    int c  = (int)(tid >> 14) & 63;
    int b  = (int)(tid >> 20) & 1;
    int p  = (int)(tid >> 21);

    const float* __restrict__ W = wd.p[p] + c * 9;
    float k00 = W[0], k01 = W[1], k02 = W[2];
    float k10 = W[3], k11 = W[4], k12 = W[5];
    float k20 = W[6], k21 = W[7], k22 = W[8];

    const float* __restrict__ src = g_T + (((long)p * BB + b) * 64 + c) * HW + (long)h * WW;
    float acc[4] = {0.f, 0.f, 0.f, 0.f};
    if (h > 0)   dwrow(src - WW, w0, k00, k01, k02, acc);
    dwrow(src, w0, k10, k11, k12, acc);
    if (h < 127) dwrow(src + WW, w0, k20, k21, k22, acc);

    float bv = bd.p[p][c];
    __nv_bfloat162 v01 = __floats2bfloat162_rn(acc[0] + bv, acc[1] + bv);
    __nv_bfloat162 v23 = __floats2bfloat162_rn(acc[2] + bv, acc[3] + bv);
    uint2 o;
    o.x = *(unsigned*)&v01; o.y = *(unsigned*)&v23;
    *(uint2*)(g_Qn + (((long)p * BB + b) * 64 + c) * HW + (long)h * WW + w0) = o;
}

// =====================================================================
// K2b: transpose Ql,Qr -> g_QT [b][h][pix][c] bf16, 64c x 64w tiles
// =====================================================================
extern "C" __global__ void __launch_bounds__(256)
k2b_transpose()
{
    __shared__ __nv_bfloat16 tile[64 * 72];
    const int t = threadIdx.x;
    const int wt = blockIdx.x, h = blockIdx.y;
    const int b = blockIdx.z & 1, p = blockIdx.z >> 1;
    const int w0 = wt * 64;
    const __nv_bfloat16* src = g_Qn + ((long)(p * BB + b) * 64) * HW + (long)h * WW + w0;

    #pragma unroll
    for (int rep = 0; rep < 2; rep++) {
        int idx = t + rep * 256;
        int c = idx >> 3, ch = idx & 7;
        *(uint4*)&tile[c * 72 + ch * 8] = *(const uint4*)(src + (long)c * HW + ch * 8);
    }
    __syncthreads();

    __nv_bfloat16* dst = g_QT + (long)p * PLANE + (((long)b * HH + h) * 512 + w0) * 64;
    #pragma unroll
    for (int rep = 0; rep < 2; rep++) {
        int idx = t + rep * 256;
        int w = idx >> 3, c0 = (idx & 7) * 8;
        unsigned short u[8];
        #pragma unroll
        for (int j = 0; j < 8; j++) u[j] = *(unsigned short*)&tile[(c0 + j) * 72 + w];
        uint4 o;
        o.x = (unsigned)u[0] | ((unsigned)u[1] << 16);
        o.y = (unsigned)u[2] | ((unsigned)u[3] << 16);
        o.z = (unsigned)u[4] | ((unsigned)u[5] << 16);
        o.w = (unsigned)u[6] | ((unsigned)u[7] << 16);
        *(uint4*)(dst + (long)w * 64 + c0) = o;
    }
}

// =====================================================================
// KATT: mma.sync bf16 attention (one direction per blockIdx.z>>1)
//   GEMM1: C[128m x 512n] = A[m,64c] @ B[n,64c]^T  (per 64-n chunk)
//   P = bf16(exp(C*scale)) stays in registers (C-frag -> A-frag layout match)
//   GEMM2: F[128m x 64c] += P_chunk @ V[c, v-chunk]^T ; normalize by rowsum
// =====================================================================
#define SM_A   0          // 128x64 bf16 = 16384
#define SM_B1  16384      // 512x64 bf16 = 65536
#define SM_V   81920      // 8 blocks of [64c][64v] bf16 = 65536
#define SM_TOT 147456

extern "C" __global__ void __launch_bounds__(256)
katt()
{
    extern __shared__ char smc[];
    const unsigned smb = smem_u32(smc);
    const int t = threadIdx.x, wid = t >> 5, lane = t & 31;
    const int wt = blockIdx.x, h = blockIdx.y;
    const int b = blockIdx.z & 1, dir = blockIdx.z >> 1;
    const int m0g = wt * 128;

    const __nv_bfloat16* Aq = g_QT + (dir ? PLANE : 0);
    const __nv_bfloat16* Bq = g_QT + (dir ? 0 : PLANE);
    const __nv_bfloat16* Vn = g_Qn + (long)(dir ? 2 : 3) * PLANE
                              + ((long)b * 64) * HW + (long)h * WW;
    float* Fo = g_F + (dir ? PLANE : 0) + ((long)b * 64) * HW + (long)h * WW + m0g;

    const long qb = (((long)b * HH + h) * 512) * 64;

    // ---- smem loads (SW128 swizzled) ----
    for (int i = t; i < 1024; i += 256) {
        int r = i >> 3, ch = i & 7;
        uint4 v = *(const uint4*)(Aq + qb + (long)(m0g + r) * 64 + ch * 8);
        *(uint4*)(smc + SM_A + SWZ(r * 128 + ch * 16)) = v;
    }
    for (int i = t; i < 4096; i += 256) {
        int r = i >> 3, ch = i & 7;
        uint4 v = *(const uint4*)(Bq + qb + (long)r * 64 + ch * 8);
        *(uint4*)(smc + SM_B1 + SWZ(r * 128 + ch * 16)) = v;
    }
    for (int i = t; i < 4096; i += 256) {
        int c = i >> 6, vv = (i & 63) * 8;
        uint4 v = *(const uint4*)(Vn + (long)c * HW + vv);
        *(uint4*)(smc + SM_V + (vv >> 6) * 8192 + SWZ(c * 128 + (vv & 63) * 2)) = v;
    }
    __syncthreads();

    // ---- A fragments (constant across chunks): 4 k16 blocks ----
    unsigned afr[4][4];
    {
        int row = wid * 16 + (lane & 15);
        int chalf = (lane >> 4) * 16;
        #pragma unroll
        for (int kb = 0; kb < 4; kb++)
            ldsm4(smb + SM_A + SWZ(row * 128 + kb * 32 + chalf), afr[kb]);
    }

    float fac[8][4];
    #pragma unroll
    for (int nt = 0; nt < 8; nt++)
        #pragma unroll
        for (int q = 0; q < 4; q++) fac[nt][q] = 0.f;
    float rs0 = 0.f, rs1 = 0.f;

    const int bn = (lane & 7) + ((lane >> 4) << 3);   // row within 16-row pair tile
    const int bk = ((lane >> 3) & 1) * 16;            // k half (16B)

    for (int ck = 0; ck < 8; ck++) {
        float cf[8][4];
        #pragma unroll
        for (int nt = 0; nt < 8; nt++)
            #pragma unroll
            for (int q = 0; q < 4; q++) cf[nt][q] = 0.f;

        // GEMM1 chunk: n = ck*64 .. +63
        unsigned b1base = smb + SM_B1 + ck * 8192;
        #pragma unroll
        for (int kb = 0; kb < 4; kb++) {
            #pragma unroll
            for (int ntp = 0; ntp < 4; ntp++) {
                unsigned bfr[4];
                ldsm4(b1base + SWZ((ntp * 16 + bn) * 128 + kb * 32 + bk), bfr);
                mma_bf16(cf[2 * ntp],     afr[kb], bfr);
                mma_bf16(cf[2 * ntp + 1], afr[kb], bfr + 2);
            }
        }

        // exp + rowsum + pack C-frags into A-frags for GEMM2
        unsigned pfr[4][4];
        #pragma unroll
        for (int nt = 0; nt < 8; nt++) {
            float e0 = __expf(cf[nt][0] * ATT_SCALE);
            float e1 = __expf(cf[nt][1] * ATT_SCALE);
            float e2 = __expf(cf[nt][2] * ATT_SCALE);
            float e3 = __expf(cf[nt][3] * ATT_SCALE);
            rs0 += e0 + e1; rs1 += e2 + e3;
            __nv_bfloat162 p01 = __floats2bfloat162_rn(e0, e1);
            __nv_bfloat162 p23 = __floats2bfloat162_rn(e2, e3);
            pfr[nt >> 1][(nt & 1) * 2 + 0] = *(unsigned*)&p01;
            pfr[nt >> 1][(nt & 1) * 2 + 1] = *(unsigned*)&p23;
        }

        // GEMM2 chunk: k = v in ck*64 .. +63, n = c 0..63
        unsigned vbase = smb + SM_V + ck * 8192;
        #pragma unroll
        for (int kb = 0; kb < 4; kb++) {
            #pragma unroll
            for (int ntp = 0; ntp < 4; ntp++) {
                unsigned bfr[4];
                ldsm4(vbase + SWZ((ntp * 16 + bn) * 128 + kb * 32 + bk), bfr);
                mma_bf16(fac[2 * ntp],     pfr[kb], bfr);
                mma_bf16(fac[2 * ntp + 1], pfr[kb], bfr + 2);
            }
        }
    }

    // rowsum reduce over the 4-lane quad (cols partitioned by lane%4)
    rs0 += __shfl_xor_sync(0xffffffffu, rs0, 1);
    rs0 += __shfl_xor_sync(0xffffffffu, rs0, 2);
    rs1 += __shfl_xor_sync(0xffffffffu, rs1, 1);
    rs1 += __shfl_xor_sync(0xffffffffu, rs1, 2);
    float inv0 = 1.f / rs0, inv1 = 1.f / rs1;

    __syncthreads();                       // A/B1 smem dead -> reuse as F staging
    float* FS = (float*)smc;               // [128 w][66 pad] fp32 = 33792B
    {
        int r0 = wid * 16 + (lane >> 2);
        #pragma unroll
        for (int nt = 0; nt < 8; nt++) {
            int c = nt * 8 + (lane & 3) * 2;
            *(float2*)&FS[r0 * 66 + c]       = make_float2(fac[nt][0] * inv0, fac[nt][1] * inv0);
            *(float2*)&FS[(r0 + 8) * 66 + c] = make_float2(fac[nt][2] * inv1, fac[nt][3] * inv1);
        }
    }
    __syncthreads();

    for (int i = t; i < 2048; i += 256) {
        int c = i >> 5, wq = (i & 31) * 4;
        float4 v = make_float4(FS[(wq + 0) * 66 + c], FS[(wq + 1) * 66 + c],
                               FS[(wq + 2) * 66 + c], FS[(wq + 3) * 66 + c]);
        *(float4*)(Fo + (long)c * HW + wq) = v;
    }
}

// =====================================================================
// K5: out = x_l + x_r + conv1x1(F_r2l, lp3) + conv1x1(F_l2r, rp3)
// =====================================================================
extern "C" __global__ void __launch_bounds__(256)
k5_out(const float* __restrict__ xl, const float* __restrict__ xr,
       const float* __restrict__ wl3, const float* __restrict__ bl3,
       const float* __restrict__ wr3, const float* __restrict__ br3,
       float* __restrict__ out)
{
    extern __shared__ float sm[];
    float* F0sm = sm;
    float* F1sm = sm + 8192;
    float* Wlsm = sm + 16384;
    float* Wrsm = sm + 16384 + 4096;

    const int t = threadIdx.x, tile = blockIdx.x, b = blockIdx.y;
    const int base = tile * 128;

    for (int idx = t; idx < 8192; idx += 256) {
        int i = idx >> 7, px = idx & 127;
        long g = ((long)b * 64 + i) * HW + base + px;
        F0sm[idx] = g_F[g];
        F1sm[idx] = g_F[PLANE + g];
    }
    for (int idx = t; idx < 4096; idx += 256) {
        int o = idx & 63, i = idx >> 6;
        Wlsm[idx] = wl3[o * 64 + i];
        Wrsm[idx] = wr3[o * 64 + i];
    }
    __syncthreads();

    const int og = t >> 5, lane = t & 31;
    float acc[8][4];
    #pragma unroll
    for (int j = 0; j < 8; j++)
        #pragma unroll
        for (int k = 0; k < 4; k++) acc[j][k] = 0.f;

    #pragma unroll 4
    for (int i = 0; i < 64; i++) {
        float f0[4], f1[4], wv0[8], wv1[8];
        #pragma unroll
        for (int k = 0; k < 4; k++) {
            f0[k] = F0sm[i * 128 + lane + 32 * k];
            f1[k] = F1sm[i * 128 + lane + 32 * k];
        }
        #pragma unroll
        for (int j = 0; j < 8; j++) {
            wv0[j] = Wlsm[i * 64 + og * 8 + j];
            wv1[j] = Wrsm[i * 64 + og * 8 + j];
        }
        #pragma unroll
        for (int j = 0; j < 8; j++)
            #pragma unroll
            for (int k = 0; k < 4; k++)
                acc[j][k] += wv0[j] * f0[k] + wv1[j] * f1[k];
    }

    #pragma unroll
    for (int j = 0; j < 8; j++) {
        int o = og * 8 + j;
        float bv = bl3[o] + br3[o];
        long ob = ((long)b * 64 + o) * HW + base;
        #pragma unroll
        for (int k = 0; k < 4; k++) {
            int px = lane + 32 * k;
            out[ob + px] = acc[j][k] + bv + xl[ob + px] + xr[ob + px];
        }
    }
}

// =====================================================================
extern "C" void kernel_launch(void* const* d_in, const int* in_sizes, int n_in,
                              void* d_out, int out_size)
{
    const float* xl = (const float*)d_in[0];
    const float* xr = (const float*)d_in[1];
    Ptrs4 w1 = {{(const float*)d_in[2],  (const float*)d_in[6],
                 (const float*)d_in[10], (const float*)d_in[14]}};
    Ptrs4 b1 = {{(const float*)d_in[3],  (const float*)d_in[7],
                 (const float*)d_in[11], (const float*)d_in[15]}};
    Ptrs4 wd = {{(const float*)d_in[4],  (const float*)d_in[8],
                 (const float*)d_in[12], (const float*)d_in[16]}};
    Ptrs4 bd = {{(const float*)d_in[5],  (const float*)d_in[9],
                 (const float*)d_in[13], (const float*)d_in[17]}};
    const float* wl3 = (const float*)d_in[18];
    const float* bl3 = (const float*)d_in[19];
    const float* wr3 = (const float*)d_in[20];
    const float* br3 = (const float*)d_in[21];

    const int smem_k1 = (64 * 256 + 64 * 64) * 4;
    const int smem_k5 = (8192 * 2 + 4096 * 2) * 4;
    cudaFuncSetAttribute(k1_conv1x1, cudaFuncAttributeMaxDynamicSharedMemorySize, smem_k1);
    cudaFuncSetAttribute(katt,       cudaFuncAttributeMaxDynamicSharedMemorySize, SM_TOT);
    cudaFuncSetAttribute(k5_out,     cudaFuncAttributeMaxDynamicSharedMemorySize, smem_k5);

    k1_conv1x1<<<dim3(256, 2, 4), 256, smem_k1>>>(xl, xr, w1, b1);
    k2_dwconv<<<32768, 256>>>(wd, bd);
    k2b_transpose<<<dim3(8, 128, 4), 256>>>();
    katt<<<dim3(4, 128, 4), 256, SM_TOT>>>();
    k5_out<<<dim3(512, 2), 256, smem_k5>>>(xl, xr, wl3, bl3, wr3, br3, (float*)d_out);
}

// round 5
// speedup vs baseline: 2.4701x; 1.3640x over previous
#include <cuda_runtime.h>
#include <cuda_bf16.h>

#define CC 64
#define BB 2
#define HH 128
#define WW 512
#define HW 65536
#define PLANE 8388608L
#define ATT_SCALE 0.125f

__device__ float         g_T[4 * PLANE];    // conv1x1 outputs fp32
__device__ __nv_bfloat16 g_Qn[4 * PLANE];   // dwconv out, natural [c][w] bf16
__device__ __nv_bfloat16 g_QT[2 * PLANE];   // Ql,Qr transposed [b][h][pix][c] bf16
__device__ float         g_F[2 * PLANE];    // F_r2l, F_l2r fp32

struct Ptrs4 { const float* p[4]; };

// ===================== helpers =====================
__device__ __forceinline__ unsigned smem_u32(const void* p) {
    unsigned a;
    asm("{ .reg .u64 t; cvta.to.shared.u64 t, %1; cvt.u32.u64 %0, t; }" : "=r"(a) : "l"(p));
    return a;
}
__device__ __forceinline__ void ldsm4(unsigned a, unsigned r[4]) {
    asm volatile("ldmatrix.sync.aligned.m8n8.x4.shared.b16 {%0,%1,%2,%3}, [%4];"
        : "=r"(r[0]), "=r"(r[1]), "=r"(r[2]), "=r"(r[3]) : "r"(a));
}
__device__ __forceinline__ void mma_bf16(float c[4], const unsigned a[4], const unsigned b[2]) {
    asm volatile("mma.sync.aligned.m16n8k16.row.col.f32.bf16.bf16.f32 "
        "{%0,%1,%2,%3}, {%4,%5,%6,%7}, {%8,%9}, {%0,%1,%2,%3};"
        : "+f"(c[0]), "+f"(c[1]), "+f"(c[2]), "+f"(c[3])
        : "r"(a[0]), "r"(a[1]), "r"(a[2]), "r"(a[3]), "r"(b[0]), "r"(b[1]));
}
__device__ __forceinline__ void cpa16(unsigned dst, const void* src) {
    asm volatile("cp.async.cg.shared.global [%0], [%1], 16;" :: "r"(dst), "l"(src));
}
#define CPA_COMMIT() asm volatile("cp.async.commit_group;" ::: "memory")
#define CPA_WAIT(n)  asm volatile("cp.async.wait_group %0;" :: "n"(n) : "memory")
#define SWZ(o) ((o) ^ (((o) >> 3) & 0x70))

// =====================================================================
// K1: conv1x1 for all 4 projections (fp32 register-tiled GEMM)
// =====================================================================
extern "C" __global__ void __launch_bounds__(256)
k1_conv1x1(const float* __restrict__ xl, const float* __restrict__ xr,
           Ptrs4 w1, Ptrs4 b1)
{
    extern __shared__ float sm[];
    float* Xsm = sm;            // [i][px] 64*256
    float* Wsm = sm + 64 * 256; // [i][o]
    const int t = threadIdx.x, tile = blockIdx.x, b = blockIdx.y, p = blockIdx.z;
    const float* __restrict__ x = (p & 1) ? xr : xl;
    const int base = tile * 256;

    #pragma unroll 4
    for (int idx = t; idx < 64 * 256; idx += 256) {
        int i = idx >> 8, px = idx & 255;
        Xsm[idx] = x[((long)(b * 64 + i)) * HW + base + px];
    }
    const float* __restrict__ w = w1.p[p];
    for (int idx = t; idx < 4096; idx += 256) {
        int o = idx & 63, i = idx >> 6;
        Wsm[idx] = w[o * 64 + i];
    }
    __syncthreads();

    const int og = t >> 5, lane = t & 31;
    float acc[8][8];
    #pragma unroll
    for (int j = 0; j < 8; j++)
        #pragma unroll
        for (int k = 0; k < 8; k++) acc[j][k] = 0.f;

    #pragma unroll 4
    for (int i = 0; i < 64; i++) {
        float wv[8], xv[8];
        #pragma unroll
        for (int j = 0; j < 8; j++) wv[j] = Wsm[i * 64 + og * 8 + j];
        #pragma unroll
        for (int k = 0; k < 8; k++) xv[k] = Xsm[i * 256 + lane + 32 * k];
        #pragma unroll
        for (int j = 0; j < 8; j++)
            #pragma unroll
            for (int k = 0; k < 8; k++) acc[j][k] += wv[j] * xv[k];
    }

    const float* __restrict__ bias = b1.p[p];
    #pragma unroll
    for (int j = 0; j < 8; j++) {
        int o = og * 8 + j;
        float bv = bias[o];
        long ob = (((long)p * BB + b) * 64 + o) * HW + base;
        #pragma unroll
        for (int k = 0; k < 8; k++)
            g_T[ob + lane + 32 * k] = acc[j][k] + bv;
    }
}

// =====================================================================
// K2: depthwise 3x3 -> bf16 natural layout
// =====================================================================
__device__ __forceinline__ void dwrow(const float* __restrict__ row, int w0,
                                      float ka, float kb, float kc, float acc[4])
{
    float4 m = *(const float4*)(row + w0);
    float l = (w0 > 0)   ? row[w0 - 1] : 0.f;
    float r = (w0 < 508) ? row[w0 + 4] : 0.f;
    float col[6] = {l, m.x, m.y, m.z, m.w, r};
    #pragma unroll
    for (int k = 0; k < 4; k++)
        acc[k] += col[k] * ka + col[k + 1] * kb + col[k + 2] * kc;
}

extern "C" __global__ void __launch_bounds__(256)
k2_dwconv(Ptrs4 wd, Ptrs4 bd)
{
    long tid = (long)blockIdx.x * 256 + threadIdx.x;
    int w0 = (int)(tid & 127) * 4;
    int h  = (int)(tid >> 7) & 127;
    int c  = (int)(tid >> 14) & 63;
    int b  = (int)(tid >> 20) & 1;
    int p  = (int)(tid >> 21);

    const float* __restrict__ W = wd.p[p] + c * 9;
    float k00 = W[0], k01 = W[1], k02 = W[2];
    float k10 = W[3], k11 = W[4], k12 = W[5];
    float k20 = W[6], k21 = W[7], k22 = W[8];

    const float* __restrict__ src = g_T + (((long)p * BB + b) * 64 + c) * HW + (long)h * WW;
    float acc[4] = {0.f, 0.f, 0.f, 0.f};
    if (h > 0)   dwrow(src - WW, w0, k00, k01, k02, acc);
    dwrow(src, w0, k10, k11, k12, acc);
    if (h < 127) dwrow(src + WW, w0, k20, k21, k22, acc);

    float bv = bd.p[p][c];
    __nv_bfloat162 v01 = __floats2bfloat162_rn(acc[0] + bv, acc[1] + bv);
    __nv_bfloat162 v23 = __floats2bfloat162_rn(acc[2] + bv, acc[3] + bv);
    uint2 o;
    o.x = *(unsigned*)&v01; o.y = *(unsigned*)&v23;
    *(uint2*)(g_Qn + (((long)p * BB + b) * 64 + c) * HW + (long)h * WW + w0) = o;
}

// =====================================================================
// K2b: transpose Ql,Qr -> g_QT [b][h][pix][c] bf16, 64c x 64w tiles
// =====================================================================
extern "C" __global__ void __launch_bounds__(256)
k2b_transpose()
{
    __shared__ __nv_bfloat16 tile[64 * 72];
    const int t = threadIdx.x;
    const int wt = blockIdx.x, h = blockIdx.y;
    const int b = blockIdx.z & 1, p = blockIdx.z >> 1;
    const int w0 = wt * 64;
    const __nv_bfloat16* src = g_Qn + ((long)(p * BB + b) * 64) * HW + (long)h * WW + w0;

    #pragma unroll
    for (int rep = 0; rep < 2; rep++) {
        int idx = t + rep * 256;
        int c = idx >> 3, ch = idx & 7;
        *(uint4*)&tile[c * 72 + ch * 8] = *(const uint4*)(src + (long)c * HW + ch * 8);
    }
    __syncthreads();

    __nv_bfloat16* dst = g_QT + (long)p * PLANE + (((long)b * HH + h) * 512 + w0) * 64;
    #pragma unroll
    for (int rep = 0; rep < 2; rep++) {
        int idx = t + rep * 256;
        int w = idx >> 3, c0 = (idx & 7) * 8;
        unsigned short u[8];
        #pragma unroll
        for (int j = 0; j < 8; j++) u[j] = *(unsigned short*)&tile[(c0 + j) * 72 + w];
        uint4 o;
        o.x = (unsigned)u[0] | ((unsigned)u[1] << 16);
        o.y = (unsigned)u[2] | ((unsigned)u[3] << 16);
        o.z = (unsigned)u[4] | ((unsigned)u[5] << 16);
        o.w = (unsigned)u[6] | ((unsigned)u[7] << 16);
        *(uint4*)(dst + (long)w * 64 + c0) = o;
    }
}

// =====================================================================
// KATT: mma.sync bf16 attention, cp.async double-buffered chunks.
//   smem: A 16K | Bbuf 2x8K | Vbuf 2x8K = 48K -> 2 CTAs/SM
// =====================================================================
#define SM_A   0          // 128x64 bf16 = 16384
#define SM_B   16384      // 2 x (64 rows x 128B)
#define SM_V   32768      // 2 x (64 rows x 128B)
#define SM_TOT 49152

extern "C" __global__ void __launch_bounds__(256, 2)
katt()
{
    extern __shared__ char smc[];
    const unsigned smb = smem_u32(smc);
    const int t = threadIdx.x, wid = t >> 5, lane = t & 31;
    const int wt = blockIdx.x, h = blockIdx.y;
    const int b = blockIdx.z & 1, dir = blockIdx.z >> 1;
    const int m0g = wt * 128;

    const __nv_bfloat16* Aq = g_QT + (dir ? PLANE : 0);
    const __nv_bfloat16* Bq = g_QT + (dir ? 0 : PLANE);
    const __nv_bfloat16* Vn = g_Qn + (long)(dir ? 2 : 3) * PLANE
                              + ((long)b * 64) * HW + (long)h * WW;
    float* Fo = g_F + (dir ? PLANE : 0) + ((long)b * 64) * HW + (long)h * WW + m0g;

    const long qb = (((long)b * HH + h) * 512) * 64;
    const __nv_bfloat16* Bqb = Bq + qb;

    // ---- chunk loader: B rows ck*64..+63 and V cols ck*64..+63, SW128 ----
    auto load_chunk = [&](int ck, int buf) {
        #pragma unroll
        for (int rep = 0; rep < 2; rep++) {
            int i = t + rep * 256;
            int r = i >> 3, ch = i & 7;
            cpa16(smb + SM_B + buf * 8192 + SWZ(r * 128 + ch * 16),
                  Bqb + (long)(ck * 64 + r) * 64 + ch * 8);
        }
        #pragma unroll
        for (int rep = 0; rep < 2; rep++) {
            int i = t + rep * 256;
            int c = i >> 3, seg = i & 7;
            cpa16(smb + SM_V + buf * 8192 + SWZ(c * 128 + seg * 16),
                  Vn + (long)c * HW + ck * 64 + seg * 8);
        }
    };

    // prologue: A + chunk0 (group0), chunk1 (group1)
    #pragma unroll
    for (int rep = 0; rep < 4; rep++) {
        int i = t + rep * 256;
        int r = i >> 3, ch = i & 7;
        cpa16(smb + SM_A + SWZ(r * 128 + ch * 16),
              Aq + qb + (long)(m0g + r) * 64 + ch * 8);
    }
    load_chunk(0, 0);
    CPA_COMMIT();
    load_chunk(1, 1);
    CPA_COMMIT();
    CPA_WAIT(1);
    __syncthreads();

    // ---- A fragments (constant across chunks) ----
    unsigned afr[4][4];
    {
        int row = wid * 16 + (lane & 15);
        int chalf = (lane >> 4) * 16;
        #pragma unroll
        for (int kb = 0; kb < 4; kb++)
            ldsm4(smb + SM_A + SWZ(row * 128 + kb * 32 + chalf), afr[kb]);
    }

    float fac[8][4];
    #pragma unroll
    for (int nt = 0; nt < 8; nt++)
        #pragma unroll
        for (int q = 0; q < 4; q++) fac[nt][q] = 0.f;
    float rs0 = 0.f, rs1 = 0.f;

    const int bn = (lane & 7) + ((lane >> 4) << 3);
    const int bk = ((lane >> 3) & 1) * 16;

    for (int ck = 0; ck < 8; ck++) {
        const int buf = ck & 1;
        float cf[8][4];
        #pragma unroll
        for (int nt = 0; nt < 8; nt++)
            #pragma unroll
            for (int q = 0; q < 4; q++) cf[nt][q] = 0.f;

        // GEMM1 chunk
        unsigned b1base = smb + SM_B + buf * 8192;
        #pragma unroll
        for (int kb = 0; kb < 4; kb++) {
            #pragma unroll
            for (int ntp = 0; ntp < 4; ntp++) {
                unsigned bfr[4];
                ldsm4(b1base + SWZ((ntp * 16 + bn) * 128 + kb * 32 + bk), bfr);
                mma_bf16(cf[2 * ntp],     afr[kb], bfr);
                mma_bf16(cf[2 * ntp + 1], afr[kb], bfr + 2);
            }
        }

        // exp + rowsum + repack C-frags as A-frags
        unsigned pfr[4][4];
        #pragma unroll
        for (int nt = 0; nt < 8; nt++) {
            float e0 = __expf(cf[nt][0] * ATT_SCALE);
            float e1 = __expf(cf[nt][1] * ATT_SCALE);
            float e2 = __expf(cf[nt][2] * ATT_SCALE);
            float e3 = __expf(cf[nt][3] * ATT_SCALE);
            rs0 += e0 + e1; rs1 += e2 + e3;
            __nv_bfloat162 p01 = __floats2bfloat162_rn(e0, e1);
            __nv_bfloat162 p23 = __floats2bfloat162_rn(e2, e3);
            pfr[nt >> 1][(nt & 1) * 2 + 0] = *(unsigned*)&p01;
            pfr[nt >> 1][(nt & 1) * 2 + 1] = *(unsigned*)&p23;
        }

        // GEMM2 chunk
        unsigned vbase = smb + SM_V + buf * 8192;
        #pragma unroll
        for (int kb = 0; kb < 4; kb++) {
            #pragma unroll
            for (int ntp = 0; ntp < 4; ntp++) {
                unsigned bfr[4];
                ldsm4(vbase + SWZ((ntp * 16 + bn) * 128 + kb * 32 + bk), bfr);
                mma_bf16(fac[2 * ntp],     pfr[kb], bfr);
                mma_bf16(fac[2 * ntp + 1], pfr[kb], bfr + 2);
            }
        }

        // pipeline: prefetch ck+2 into the buffer just consumed
        if (ck < 7) {
            __syncthreads();
            if (ck + 2 < 8) {
                load_chunk(ck + 2, buf);
                CPA_COMMIT();
                CPA_WAIT(1);
            } else {
                CPA_WAIT(0);
            }
            __syncthreads();
        }
    }

    // rowsum reduce over 4-lane quad (cols partitioned by lane%4)
    rs0 += __shfl_xor_sync(0xffffffffu, rs0, 1);
    rs0 += __shfl_xor_sync(0xffffffffu, rs0, 2);
    rs1 += __shfl_xor_sync(0xffffffffu, rs1, 1);
    rs1 += __shfl_xor_sync(0xffffffffu, rs1, 2);
    float inv0 = 1.f / rs0, inv1 = 1.f / rs1;

    __syncthreads();                       // smem dead -> reuse as F staging
    float* FS = (float*)smc;               // [128 w][66 pad] fp32 = 33792B
    {
        int r0 = wid * 16 + (lane >> 2);
        #pragma unroll
        for (int nt = 0; nt < 8; nt++) {
            int c = nt * 8 + (lane & 3) * 2;
            *(float2*)&FS[r0 * 66 + c]       = make_float2(fac[nt][0] * inv0, fac[nt][1] * inv0);
            *(float2*)&FS[(r0 + 8) * 66 + c] = make_float2(fac[nt][2] * inv1, fac[nt][3] * inv1);
        }
    }
    __syncthreads();

    for (int i = t; i < 2048; i += 256) {
        int c = i >> 5, wq = (i & 31) * 4;
        float4 v = make_float4(FS[(wq + 0) * 66 + c], FS[(wq + 1) * 66 + c],
                               FS[(wq + 2) * 66 + c], FS[(wq + 3) * 66 + c]);
        *(float4*)(Fo + (long)c * HW + wq) = v;
    }
}

// =====================================================================
// K5: out = x_l + x_r + conv1x1(F_r2l, lp3) + conv1x1(F_l2r, rp3)
// =====================================================================
extern "C" __global__ void __launch_bounds__(256)
k5_out(const float* __restrict__ xl, const float* __restrict__ xr,
       const float* __restrict__ wl3, const float* __restrict__ bl3,
       const float* __restrict__ wr3, const float* __restrict__ br3,
       float* __restrict__ out)
{
    extern __shared__ float sm[];
    float* F0sm = sm;
    float* F1sm = sm + 8192;
    float* Wlsm = sm + 16384;
    float* Wrsm = sm + 16384 + 4096;

    const int t = threadIdx.x, tile = blockIdx.x, b = blockIdx.y;
    const int base = tile * 128;

    for (int idx = t; idx < 8192; idx += 256) {
        int i = idx >> 7, px = idx & 127;
        long g = ((long)b * 64 + i) * HW + base + px;
        F0sm[idx] = g_F[g];
        F1sm[idx] = g_F[PLANE + g];
    }
    for (int idx = t; idx < 4096; idx += 256) {
        int o = idx & 63, i = idx >> 6;
        Wlsm[idx] = wl3[o * 64 + i];
        Wrsm[idx] = wr3[o * 64 + i];
    }
    __syncthreads();

    const int og = t >> 5, lane = t & 31;
    float acc[8][4];
    #pragma unroll
    for (int j = 0; j < 8; j++)
        #pragma unroll
        for (int k = 0; k < 4; k++) acc[j][k] = 0.f;

    #pragma unroll 4
    for (int i = 0; i < 64; i++) {
        float f0[4], f1[4], wv0[8], wv1[8];
        #pragma unroll
        for (int k = 0; k < 4; k++) {
            f0[k] = F0sm[i * 128 + lane + 32 * k];
            f1[k] = F1sm[i * 128 + lane + 32 * k];
        }
        #pragma unroll
        for (int j = 0; j < 8; j++) {
            wv0[j] = Wlsm[i * 64 + og * 8 + j];
            wv1[j] = Wrsm[i * 64 + og * 8 + j];
        }
        #pragma unroll
        for (int j = 0; j < 8; j++)
            #pragma unroll
            for (int k = 0; k < 4; k++)
                acc[j][k] += wv0[j] * f0[k] + wv1[j] * f1[k];
    }

    #pragma unroll
    for (int j = 0; j < 8; j++) {
        int o = og * 8 + j;
        float bv = bl3[o] + br3[o];
        long ob = ((long)b * 64 + o) * HW + base;
        #pragma unroll
        for (int k = 0; k < 4; k++) {
            int px = lane + 32 * k;
            out[ob + px] = acc[j][k] + bv + xl[ob + px] + xr[ob + px];
        }
    }
}

// =====================================================================
extern "C" void kernel_launch(void* const* d_in, const int* in_sizes, int n_in,
                              void* d_out, int out_size)
{
    const float* xl = (const float*)d_in[0];
    const float* xr = (const float*)d_in[1];
    Ptrs4 w1 = {{(const float*)d_in[2],  (const float*)d_in[6],
                 (const float*)d_in[10], (const float*)d_in[14]}};
    Ptrs4 b1 = {{(const float*)d_in[3],  (const float*)d_in[7],
                 (const float*)d_in[11], (const float*)d_in[15]}};
    Ptrs4 wd = {{(const float*)d_in[4],  (const float*)d_in[8],
                 (const float*)d_in[12], (const float*)d_in[16]}};
    Ptrs4 bd = {{(const float*)d_in[5],  (const float*)d_in[9],
                 (const float*)d_in[13], (const float*)d_in[17]}};
    const float* wl3 = (const float*)d_in[18];
    const float* bl3 = (const float*)d_in[19];
    const float* wr3 = (const float*)d_in[20];
    const float* br3 = (const float*)d_in[21];

    const int smem_k1 = (64 * 256 + 64 * 64) * 4;
    const int smem_k5 = (8192 * 2 + 4096 * 2) * 4;
    cudaFuncSetAttribute(k1_conv1x1, cudaFuncAttributeMaxDynamicSharedMemorySize, smem_k1);
    cudaFuncSetAttribute(katt,       cudaFuncAttributeMaxDynamicSharedMemorySize, SM_TOT);
    cudaFuncSetAttribute(k5_out,     cudaFuncAttributeMaxDynamicSharedMemorySize, smem_k5);

    k1_conv1x1<<<dim3(256, 2, 4), 256, smem_k1>>>(xl, xr, w1, b1);
    k2_dwconv<<<32768, 256>>>(wd, bd);
    k2b_transpose<<<dim3(8, 128, 4), 256>>>();
    katt<<<dim3(4, 128, 4), 256, SM_TOT>>>();
    k5_out<<<dim3(512, 2), 256, smem_k5>>>(xl, xr, wl3, bl3, wr3, br3, (float*)d_out);
}

// round 6
// speedup vs baseline: 2.8531x; 1.1551x over previous
#include <cuda_runtime.h>
#include <cuda_bf16.h>

#define CC 64
#define BB 2
#define HH 128
#define WW 512
#define HW 65536
#define PLANE 8388608L
#define ATT_SCALE 0.125f

__device__ __nv_bfloat16 g_xT[2 * PLANE];   // x transposed bf16 [side][b][hw][c]
__device__ __nv_bfloat16 g_T[4 * PLANE];    // conv1x1 out bf16 natural [p][b][c][hw]
__device__ __nv_bfloat16 g_Qn[4 * PLANE];   // dwconv out bf16 natural
__device__ __nv_bfloat16 g_QT[2 * PLANE];   // Ql,Qr transposed [p][b][hw][c]
__device__ __nv_bfloat16 g_FT[2 * PLANE];   // F transposed bf16 [dir][b][hw][c]

struct Ptrs4 { const float* p[4]; };

// ===================== helpers =====================
__device__ __forceinline__ unsigned smem_u32(const void* p) {
    unsigned a;
    asm("{ .reg .u64 t; cvta.to.shared.u64 t, %1; cvt.u32.u64 %0, t; }" : "=r"(a) : "l"(p));
    return a;
}
__device__ __forceinline__ void ldsm4(unsigned a, unsigned r[4]) {
    asm volatile("ldmatrix.sync.aligned.m8n8.x4.shared.b16 {%0,%1,%2,%3}, [%4];"
        : "=r"(r[0]), "=r"(r[1]), "=r"(r[2]), "=r"(r[3]) : "r"(a));
}
__device__ __forceinline__ void mma_bf16(float c[4], const unsigned a[4], const unsigned b[2]) {
    asm volatile("mma.sync.aligned.m16n8k16.row.col.f32.bf16.bf16.f32 "
        "{%0,%1,%2,%3}, {%4,%5,%6,%7}, {%8,%9}, {%0,%1,%2,%3};"
        : "+f"(c[0]), "+f"(c[1]), "+f"(c[2]), "+f"(c[3])
        : "r"(a[0]), "r"(a[1]), "r"(a[2]), "r"(a[3]), "r"(b[0]), "r"(b[1]));
}
__device__ __forceinline__ void cpa16(unsigned dst, const void* src) {
    asm volatile("cp.async.cg.shared.global [%0], [%1], 16;" :: "r"(dst), "l"(src));
}
#define CPA_COMMIT() asm volatile("cp.async.commit_group;" ::: "memory")
#define CPA_WAIT(n)  asm volatile("cp.async.wait_group %0;" :: "n"(n) : "memory")
#define SWZ(o) ((o) ^ (((o) >> 3) & 0x70))

// load fp32 W row-chunk, convert, store bf16 swizzled [o][i] rows of 128B
__device__ __forceinline__ void w_to_smem(const float* __restrict__ w, char* dst, int t)
{
    int o = t >> 2, seg = t & 3;
    const float* ws = w + o * 64 + seg * 16;
    float f[16];
    #pragma unroll
    for (int j = 0; j < 4; j++) *(float4*)&f[j * 4] = *(const float4*)(ws + j * 4);
    unsigned u[8];
    #pragma unroll
    for (int j = 0; j < 8; j++) {
        __nv_bfloat162 h2 = __floats2bfloat162_rn(f[2 * j], f[2 * j + 1]);
        u[j] = *(unsigned*)&h2;
    }
    *(uint4*)(dst + SWZ(o * 128 + seg * 32))      = make_uint4(u[0], u[1], u[2], u[3]);
    *(uint4*)(dst + SWZ(o * 128 + seg * 32 + 16)) = make_uint4(u[4], u[5], u[6], u[7]);
}

// =====================================================================
// KX: transpose + convert x -> g_xT [side][b][hw][c] bf16, 64c x 64px tiles
// =====================================================================
extern "C" __global__ void __launch_bounds__(256)
kx_transpose(const float* __restrict__ xl, const float* __restrict__ xr)
{
    __shared__ __nv_bfloat16 tile[64 * 72];
    const int t = threadIdx.x;
    const int tl = blockIdx.x, b = blockIdx.y, side = blockIdx.z;
    const int px0 = tl * 64;
    const float* __restrict__ x = side ? xr : xl;

    #pragma unroll
    for (int rep = 0; rep < 2; rep++) {
        int idx = t + rep * 256;
        int c = idx >> 3, ch = (idx & 7) * 8;
        const float* s = x + ((long)(b * 64 + c)) * HW + px0 + ch;
        float4 f0 = *(const float4*)s, f1 = *(const float4*)(s + 4);
        __nv_bfloat162 h0 = __floats2bfloat162_rn(f0.x, f0.y);
        __nv_bfloat162 h1 = __floats2bfloat162_rn(f0.z, f0.w);
        __nv_bfloat162 h2 = __floats2bfloat162_rn(f1.x, f1.y);
        __nv_bfloat162 h3 = __floats2bfloat162_rn(f1.z, f1.w);
        *(uint4*)&tile[c * 72 + ch] = make_uint4(*(unsigned*)&h0, *(unsigned*)&h1,
                                                 *(unsigned*)&h2, *(unsigned*)&h3);
    }
    __syncthreads();

    __nv_bfloat16* dst = g_xT + (long)side * PLANE + ((long)b * HW + px0) * 64;
    #pragma unroll
    for (int rep = 0; rep < 2; rep++) {
        int idx = t + rep * 256;
        int w = idx >> 3, c0 = (idx & 7) * 8;
        unsigned short u[8];
        #pragma unroll
        for (int j = 0; j < 8; j++) u[j] = *(unsigned short*)&tile[(c0 + j) * 72 + w];
        uint4 o;
        o.x = (unsigned)u[0] | ((unsigned)u[1] << 16);
        o.y = (unsigned)u[2] | ((unsigned)u[3] << 16);
        o.z = (unsigned)u[4] | ((unsigned)u[5] << 16);
        o.w = (unsigned)u[6] | ((unsigned)u[7] << 16);
        *(uint4*)(dst + (long)w * 64 + c0) = o;
    }
}

// =====================================================================
// K1H: conv1x1 via HMMA. C[px][o] = sum_i xT[px][i] * W[o][i] + bias[o]
//   output staged -> bf16 g_T natural [c][hw]
// =====================================================================
#define K1_A    0
#define K1_W    16384
#define K1_BIAS 24576
#define K1_TOT  24832

extern "C" __global__ void __launch_bounds__(256)
k1h(Ptrs4 w1, Ptrs4 b1)
{
    extern __shared__ char smc[];
    const unsigned smb = smem_u32(smc);
    const int t = threadIdx.x, wid = t >> 5, lane = t & 31;
    const int tile = blockIdx.x, b = blockIdx.y, p = blockIdx.z;
    const int side = p & 1, px0 = tile * 128;

    const __nv_bfloat16* xT = g_xT + (long)side * PLANE + ((long)b * HW + px0) * 64;
    #pragma unroll
    for (int rep = 0; rep < 4; rep++) {
        int i = t + rep * 256;
        int r = i >> 3, ch = i & 7;
        cpa16(smb + K1_A + SWZ(r * 128 + ch * 16), xT + (long)r * 64 + ch * 8);
    }
    CPA_COMMIT();
    w_to_smem(w1.p[p], smc + K1_W, t);
    if (t < 64) ((float*)(smc + K1_BIAS))[t] = b1.p[p][t];
    CPA_WAIT(0);
    __syncthreads();

    unsigned afr[4][4];
    {
        int row = wid * 16 + (lane & 15);
        int chalf = (lane >> 4) * 16;
        #pragma unroll
        for (int kb = 0; kb < 4; kb++)
            ldsm4(smb + K1_A + SWZ(row * 128 + kb * 32 + chalf), afr[kb]);
    }

    const int bn = (lane & 7) + ((lane >> 4) << 3);
    const int bk = ((lane >> 3) & 1) * 16;
    float cf[8][4];
    #pragma unroll
    for (int nt = 0; nt < 8; nt++)
        #pragma unroll
        for (int q = 0; q < 4; q++) cf[nt][q] = 0.f;

    #pragma unroll
    for (int kb = 0; kb < 4; kb++) {
        #pragma unroll
        for (int ntp = 0; ntp < 4; ntp++) {
            unsigned bfr[4];
            ldsm4(smb + K1_W + SWZ((ntp * 16 + bn) * 128 + kb * 32 + bk), bfr);
            mma_bf16(cf[2 * ntp],     afr[kb], bfr);
            mma_bf16(cf[2 * ntp + 1], afr[kb], bfr + 2);
        }
    }

    __syncthreads();                      // A/W dead -> stage region
    __nv_bfloat16* TS = (__nv_bfloat16*)smc;      // [64 o][136 px]
    const float* bias = (const float*)(smc + K1_BIAS);
    {
        int r0 = wid * 16 + (lane >> 2);
        #pragma unroll
        for (int nt = 0; nt < 8; nt++) {
            int c = nt * 8 + (lane & 3) * 2;
            float b0 = bias[c], b1v = bias[c + 1];
            TS[c * 136 + r0]           = __float2bfloat16_rn(cf[nt][0] + b0);
            TS[(c + 1) * 136 + r0]     = __float2bfloat16_rn(cf[nt][1] + b1v);
            TS[c * 136 + r0 + 8]       = __float2bfloat16_rn(cf[nt][2] + b0);
            TS[(c + 1) * 136 + r0 + 8] = __float2bfloat16_rn(cf[nt][3] + b1v);
        }
    }
    __syncthreads();

    __nv_bfloat16* To = g_T + (((long)p * BB + b) * 64) * HW + px0;
    #pragma unroll
    for (int rep = 0; rep < 4; rep++) {
        int idx = t + rep * 256;
        int row = idx >> 4, seg = idx & 15;
        *(uint4*)(To + (long)row * HW + seg * 8) = *(uint4*)&TS[row * 136 + seg * 8];
    }
}

// =====================================================================
// K2: depthwise 3x3 on bf16 T -> bf16 natural g_Qn (fp32 accumulate)
// =====================================================================
__device__ __forceinline__ void dwrow_bf(const __nv_bfloat16* __restrict__ row, int w0,
                                         float ka, float kb, float kc, float acc[4])
{
    const __nv_bfloat162* r2 = (const __nv_bfloat162*)(row + w0);
    float2 a01 = __bfloat1622float2(r2[0]);
    float2 a23 = __bfloat1622float2(r2[1]);
    float l = (w0 > 0)   ? __bfloat162float(row[w0 - 1]) : 0.f;
    float r = (w0 < 508) ? __bfloat162float(row[w0 + 4]) : 0.f;
    float col[6] = {l, a01.x, a01.y, a23.x, a23.y, r};
    #pragma unroll
    for (int k = 0; k < 4; k++)
        acc[k] += col[k] * ka + col[k + 1] * kb + col[k + 2] * kc;
}

extern "C" __global__ void __launch_bounds__(256)
k2_dwconv(Ptrs4 wd, Ptrs4 bd)
{
    long tid = (long)blockIdx.x * 256 + threadIdx.x;
    int w0 = (int)(tid & 127) * 4;
    int h  = (int)(tid >> 7) & 127;
    int c  = (int)(tid >> 14) & 63;
    int b  = (int)(tid >> 20) & 1;
    int p  = (int)(tid >> 21);

    const float* __restrict__ W = wd.p[p] + c * 9;
    float k00 = W[0], k01 = W[1], k02 = W[2];
    float k10 = W[3], k11 = W[4], k12 = W[5];
    float k20 = W[6], k21 = W[7], k22 = W[8];

    const __nv_bfloat16* __restrict__ src =
        g_T + (((long)p * BB + b) * 64 + c) * HW + (long)h * WW;
    float acc[4] = {0.f, 0.f, 0.f, 0.f};
    if (h > 0)   dwrow_bf(src - WW, w0, k00, k01, k02, acc);
    dwrow_bf(src, w0, k10, k11, k12, acc);
    if (h < 127) dwrow_bf(src + WW, w0, k20, k21, k22, acc);

    float bv = bd.p[p][c];
    __nv_bfloat162 v01 = __floats2bfloat162_rn(acc[0] + bv, acc[1] + bv);
    __nv_bfloat162 v23 = __floats2bfloat162_rn(acc[2] + bv, acc[3] + bv);
    uint2 o;
    o.x = *(unsigned*)&v01; o.y = *(unsigned*)&v23;
    *(uint2*)(g_Qn + (((long)p * BB + b) * 64 + c) * HW + (long)h * WW + w0) = o;
}

// =====================================================================
// K2b: transpose Ql,Qr -> g_QT [b][h][pix][c] bf16, 64c x 64w tiles
// =====================================================================
extern "C" __global__ void __launch_bounds__(256)
k2b_transpose()
{
    __shared__ __nv_bfloat16 tile[64 * 72];
    const int t = threadIdx.x;
    const int wt = blockIdx.x, h = blockIdx.y;
    const int b = blockIdx.z & 1, p = blockIdx.z >> 1;
    const int w0 = wt * 64;
    const __nv_bfloat16* src = g_Qn + ((long)(p * BB + b) * 64) * HW + (long)h * WW + w0;

    #pragma unroll
    for (int rep = 0; rep < 2; rep++) {
        int idx = t + rep * 256;
        int c = idx >> 3, ch = idx & 7;
        *(uint4*)&tile[c * 72 + ch * 8] = *(const uint4*)(src + (long)c * HW + ch * 8);
    }
    __syncthreads();

    __nv_bfloat16* dst = g_QT + (long)p * PLANE + (((long)b * HH + h) * 512 + w0) * 64;
    #pragma unroll
    for (int rep = 0; rep < 2; rep++) {
        int idx = t + rep * 256;
        int w = idx >> 3, c0 = (idx & 7) * 8;
        unsigned short u[8];
        #pragma unroll
        for (int j = 0; j < 8; j++) u[j] = *(unsigned short*)&tile[(c0 + j) * 72 + w];
        uint4 o;
        o.x = (unsigned)u[0] | ((unsigned)u[1] << 16);
        o.y = (unsigned)u[2] | ((unsigned)u[3] << 16);
        o.z = (unsigned)u[4] | ((unsigned)u[5] << 16);
        o.w = (unsigned)u[6] | ((unsigned)u[7] << 16);
        *(uint4*)(dst + (long)w * 64 + c0) = o;
    }
}

// =====================================================================
// KATT: mma.sync bf16 attention, cp.async double-buffered chunks.
//   smem: A 16K | Bbuf 2x8K | Vbuf 2x8K = 48K -> 2 CTAs/SM
//   output: F transposed bf16 [px][c] -> g_FT
// =====================================================================
#define SM_A   0
#define SM_B   16384
#define SM_V   32768
#define SM_TOT 49152

extern "C" __global__ void __launch_bounds__(256, 2)
katt()
{
    extern __shared__ char smc[];
    const unsigned smb = smem_u32(smc);
    const int t = threadIdx.x, wid = t >> 5, lane = t & 31;
    const int wt = blockIdx.x, h = blockIdx.y;
    const int b = blockIdx.z & 1, dir = blockIdx.z >> 1;
    const int m0g = wt * 128;

    const __nv_bfloat16* Aq = g_QT + (dir ? PLANE : 0);
    const __nv_bfloat16* Bq = g_QT + (dir ? 0 : PLANE);
    const __nv_bfloat16* Vn = g_Qn + (long)(dir ? 2 : 3) * PLANE
                              + ((long)b * 64) * HW + (long)h * WW;

    const long qb = (((long)b * HH + h) * 512) * 64;
    const __nv_bfloat16* Bqb = Bq + qb;

    auto load_chunk = [&](int ck, int buf) {
        #pragma unroll
        for (int rep = 0; rep < 2; rep++) {
            int i = t + rep * 256;
            int r = i >> 3, ch = i & 7;
            cpa16(smb + SM_B + buf * 8192 + SWZ(r * 128 + ch * 16),
                  Bqb + (long)(ck * 64 + r) * 64 + ch * 8);
        }
        #pragma unroll
        for (int rep = 0; rep < 2; rep++) {
            int i = t + rep * 256;
            int c = i >> 3, seg = i & 7;
            cpa16(smb + SM_V + buf * 8192 + SWZ(c * 128 + seg * 16),
                  Vn + (long)c * HW + ck * 64 + seg * 8);
        }
    };

    #pragma unroll
    for (int rep = 0; rep < 4; rep++) {
        int i = t + rep * 256;
        int r = i >> 3, ch = i & 7;
        cpa16(smb + SM_A + SWZ(r * 128 + ch * 16),
              Aq + qb + (long)(m0g + r) * 64 + ch * 8);
    }
    load_chunk(0, 0);
    CPA_COMMIT();
    load_chunk(1, 1);
    CPA_COMMIT();
    CPA_WAIT(1);
    __syncthreads();

    unsigned afr[4][4];
    {
        int row = wid * 16 + (lane & 15);
        int chalf = (lane >> 4) * 16;
        #pragma unroll
        for (int kb = 0; kb < 4; kb++)
            ldsm4(smb + SM_A + SWZ(row * 128 + kb * 32 + chalf), afr[kb]);
    }

    float fac[8][4];
    #pragma unroll
    for (int nt = 0; nt < 8; nt++)
        #pragma unroll
        for (int q = 0; q < 4; q++) fac[nt][q] = 0.f;
    float rs0 = 0.f, rs1 = 0.f;

    const int bn = (lane & 7) + ((lane >> 4) << 3);
    const int bk = ((lane >> 3) & 1) * 16;

    for (int ck = 0; ck < 8; ck++) {
        const int buf = ck & 1;
        float cf[8][4];
        #pragma unroll
        for (int nt = 0; nt < 8; nt++)
            #pragma unroll
            for (int q = 0; q < 4; q++) cf[nt][q] = 0.f;

        unsigned b1base = smb + SM_B + buf * 8192;
        #pragma unroll
        for (int kb = 0; kb < 4; kb++) {
            #pragma unroll
            for (int ntp = 0; ntp < 4; ntp++) {
                unsigned bfr[4];
                ldsm4(b1base + SWZ((ntp * 16 + bn) * 128 + kb * 32 + bk), bfr);
                mma_bf16(cf[2 * ntp],     afr[kb], bfr);
                mma_bf16(cf[2 * ntp + 1], afr[kb], bfr + 2);
            }
        }

        unsigned pfr[4][4];
        #pragma unroll
        for (int nt = 0; nt < 8; nt++) {
            float e0 = __expf(cf[nt][0] * ATT_SCALE);
            float e1 = __expf(cf[nt][1] * ATT_SCALE);
            float e2 = __expf(cf[nt][2] * ATT_SCALE);
            float e3 = __expf(cf[nt][3] * ATT_SCALE);
            rs0 += e0 + e1; rs1 += e2 + e3;
            __nv_bfloat162 p01 = __floats2bfloat162_rn(e0, e1);
            __nv_bfloat162 p23 = __floats2bfloat162_rn(e2, e3);
            pfr[nt >> 1][(nt & 1) * 2 + 0] = *(unsigned*)&p01;
            pfr[nt >> 1][(nt & 1) * 2 + 1] = *(unsigned*)&p23;
        }

        unsigned vbase = smb + SM_V + buf * 8192;
        #pragma unroll
        for (int kb = 0; kb < 4; kb++) {
            #pragma unroll
            for (int ntp = 0; ntp < 4; ntp++) {
                unsigned bfr[4];
                ldsm4(vbase + SWZ((ntp * 16 + bn) * 128 + kb * 32 + bk), bfr);
                mma_bf16(fac[2 * ntp],     pfr[kb], bfr);
                mma_bf16(fac[2 * ntp + 1], pfr[kb], bfr + 2);
            }
        }

        if (ck < 7) {
            __syncthreads();
            if (ck + 2 < 8) {
                load_chunk(ck + 2, buf);
                CPA_COMMIT();
                CPA_WAIT(1);
            } else {
                CPA_WAIT(0);
            }
            __syncthreads();
        }
    }

    rs0 += __shfl_xor_sync(0xffffffffu, rs0, 1);
    rs0 += __shfl_xor_sync(0xffffffffu, rs0, 2);
    rs1 += __shfl_xor_sync(0xffffffffu, rs1, 1);
    rs1 += __shfl_xor_sync(0xffffffffu, rs1, 2);
    float inv0 = 1.f / rs0, inv1 = 1.f / rs1;

    __syncthreads();                      // smem dead -> F staging
    __nv_bfloat16* FSh = (__nv_bfloat16*)smc;     // [128 px][72 c]
    {
        int r0 = wid * 16 + (lane >> 2);
        #pragma unroll
        for (int nt = 0; nt < 8; nt++) {
            int c = nt * 8 + (lane & 3) * 2;
            __nv_bfloat162 p0 = __floats2bfloat162_rn(fac[nt][0] * inv0, fac[nt][1] * inv0);
            __nv_bfloat162 p1 = __floats2bfloat162_rn(fac[nt][2] * inv1, fac[nt][3] * inv1);
            *(__nv_bfloat162*)&FSh[r0 * 72 + c]       = p0;
            *(__nv_bfloat162*)&FSh[(r0 + 8) * 72 + c] = p1;
        }
    }
    __syncthreads();

    __nv_bfloat16* FoT = g_FT + (long)dir * PLANE
                         + ((long)b * HW + (long)h * WW + m0g) * 64;
    #pragma unroll
    for (int rep = 0; rep < 4; rep++) {
        int idx = t + rep * 256;
        int px = idx >> 3, seg = idx & 7;
        *(uint4*)(FoT + (long)px * 64 + seg * 8) = *(uint4*)&FSh[px * 72 + seg * 8];
    }
}

// =====================================================================
// K5H: out = x_l + x_r + conv1x1(F0,lp3) + conv1x1(F1,rp3) via HMMA
// =====================================================================
#define K5_A0  0
#define K5_A1  16384
#define K5_W   32768
#define K5_BS  49152
#define K5_TOT 49408

extern "C" __global__ void __launch_bounds__(256)
k5h(const float* __restrict__ xl, const float* __restrict__ xr,
    const float* __restrict__ wl3, const float* __restrict__ bl3,
    const float* __restrict__ wr3, const float* __restrict__ br3,
    float* __restrict__ out)
{
    extern __shared__ char smc[];
    const unsigned smb = smem_u32(smc);
    const int t = threadIdx.x, wid = t >> 5, lane = t & 31;
    const int tile = blockIdx.x, b = blockIdx.y;
    const int px0 = tile * 128;

    #pragma unroll
    for (int d = 0; d < 2; d++) {
        const __nv_bfloat16* FT = g_FT + (long)d * PLANE + ((long)b * HW + px0) * 64;
        #pragma unroll
        for (int rep = 0; rep < 4; rep++) {
            int i = t + rep * 256;
            int r = i >> 3, ch = i & 7;
            cpa16(smb + K5_A0 + d * 16384 + SWZ(r * 128 + ch * 16), FT + (long)r * 64 + ch * 8);
        }
    }
    CPA_COMMIT();
    w_to_smem(wl3, smc + K5_W, t);
    w_to_smem(wr3, smc + K5_W + 8192, t);
    if (t < 64) ((float*)(smc + K5_BS))[t] = bl3[t] + br3[t];
    CPA_WAIT(0);
    __syncthreads();

    unsigned afr0[4][4], afr1[4][4];
    {
        int row = wid * 16 + (lane & 15);
        int chalf = (lane >> 4) * 16;
        #pragma unroll
        for (int kb = 0; kb < 4; kb++) {
            ldsm4(smb + K5_A0 + SWZ(row * 128 + kb * 32 + chalf), afr0[kb]);
            ldsm4(smb + K5_A1 + SWZ(row * 128 + kb * 32 + chalf), afr1[kb]);
        }
    }

    const int bn = (lane & 7) + ((lane >> 4) << 3);
    const int bk = ((lane >> 3) & 1) * 16;
    float cf[8][4];
    #pragma unroll
    for (int nt = 0; nt < 8; nt++)
        #pragma unroll
        for (int q = 0; q < 4; q++) cf[nt][q] = 0.f;

    #pragma unroll
    for (int kb = 0; kb < 4; kb++) {
        #pragma unroll
        for (int ntp = 0; ntp < 4; ntp++) {
            unsigned bfr[4];
            ldsm4(smb + K5_W + SWZ((ntp * 16 + bn) * 128 + kb * 32 + bk), bfr);
            mma_bf16(cf[2 * ntp],     afr0[kb], bfr);
            mma_bf16(cf[2 * ntp + 1], afr0[kb], bfr + 2);
            ldsm4(smb + K5_W + 8192 + SWZ((ntp * 16 + bn) * 128 + kb * 32 + bk), bfr);
            mma_bf16(cf[2 * ntp],     afr1[kb], bfr);
            mma_bf16(cf[2 * ntp + 1], afr1[kb], bfr + 2);
        }
    }

    __syncthreads();                      // A/W dead -> stage fp32 [64 o][136 px]
    float* TS = (float*)smc;
    const float* bias = (const float*)(smc + K5_BS);
    {
        int r0 = wid * 16 + (lane >> 2);
        #pragma unroll
        for (int nt = 0; nt < 8; nt++) {
            int c = nt * 8 + (lane & 3) * 2;
            float b0 = bias[c], b1v = bias[c + 1];
            TS[c * 136 + r0]           = cf[nt][0] + b0;
            TS[(c + 1) * 136 + r0]     = cf[nt][1] + b1v;
            TS[c * 136 + r0 + 8]       = cf[nt][2] + b0;
            TS[(c + 1) * 136 + r0 + 8] = cf[nt][3] + b1v;
        }
    }
    __syncthreads();

    #pragma unroll
    for (int rep = 0; rep < 8; rep++) {
        int idx = t + rep * 256;
        int row = idx >> 5, seg = (idx & 31) * 4;
        float4 v = *(float4*)&TS[row * 136 + seg];
        long ob = ((long)b * 64 + row) * HW + px0 + seg;
        float4 a = *(const float4*)(xl + ob);
        float4 c = *(const float4*)(xr + ob);
        v.x += a.x + c.x; v.y += a.y + c.y;
        v.z += a.z + c.z; v.w += a.w + c.w;
        *(float4*)(out + ob) = v;
    }
}

// =====================================================================
extern "C" void kernel_launch(void* const* d_in, const int* in_sizes, int n_in,
                              void* d_out, int out_size)
{
    const float* xl = (const float*)d_in[0];
    const float* xr = (const float*)d_in[1];
    Ptrs4 w1 = {{(const float*)d_in[2],  (const float*)d_in[6],
                 (const float*)d_in[10], (const float*)d_in[14]}};
    Ptrs4 b1 = {{(const float*)d_in[3],  (const float*)d_in[7],
                 (const float*)d_in[11], (const float*)d_in[15]}};
    Ptrs4 wd = {{(const float*)d_in[4],  (const float*)d_in[8],
                 (const float*)d_in[12], (const float*)d_in[16]}};
    Ptrs4 bd = {{(const float*)d_in[5],  (const float*)d_in[9],
                 (const float*)d_in[13], (const float*)d_in[17]}};
    const float* wl3 = (const float*)d_in[18];
    const float* bl3 = (const float*)d_in[19];
    const float* wr3 = (const float*)d_in[20];
    const float* br3 = (const float*)d_in[21];

    cudaFuncSetAttribute(katt, cudaFuncAttributeMaxDynamicSharedMemorySize, SM_TOT);
    cudaFuncSetAttribute(k5h,  cudaFuncAttributeMaxDynamicSharedMemorySize, K5_TOT);

    kx_transpose<<<dim3(1024, 2, 2), 256>>>(xl, xr);
    k1h<<<dim3(512, 2, 4), 256, K1_TOT>>>(w1, b1);
    k2_dwconv<<<32768, 256>>>(wd, bd);
    k2b_transpose<<<dim3(8, 128, 4), 256>>>();
    katt<<<dim3(4, 128, 4), 256, SM_TOT>>>();
    k5h<<<dim3(512, 2), 256, K5_TOT>>>(xl, xr, wl3, bl3, wr3, br3, (float*)d_out);
}

// round 7
// speedup vs baseline: 4.3299x; 1.5176x over previous
#include <cuda_runtime.h>
#include <cuda_bf16.h>

#define CC 64
#define BB 2
#define HH 128
#define WW 512
#define HW 65536
#define PLANE 8388608L
#define ATT_SCALE 0.125f

__device__ __nv_bfloat16 g_T[4 * PLANE];    // conv1x1 out bf16 natural [p][b][c][hw]
__device__ __nv_bfloat16 g_Qn[4 * PLANE];   // dwconv out bf16 natural
__device__ __nv_bfloat16 g_FT[2 * PLANE];   // F transposed bf16 [dir][b][hw][c]

struct Ptrs4 { const float* p[4]; };

// ===================== helpers =====================
__device__ __forceinline__ unsigned smem_u32(const void* p) {
    unsigned a;
    asm("{ .reg .u64 t; cvta.to.shared.u64 t, %1; cvt.u32.u64 %0, t; }" : "=r"(a) : "l"(p));
    return a;
}
__device__ __forceinline__ void ldsm4(unsigned a, unsigned r[4]) {
    asm volatile("ldmatrix.sync.aligned.m8n8.x4.shared.b16 {%0,%1,%2,%3}, [%4];"
        : "=r"(r[0]), "=r"(r[1]), "=r"(r[2]), "=r"(r[3]) : "r"(a));
}
__device__ __forceinline__ void ldsm4t(unsigned a, unsigned r[4]) {
    asm volatile("ldmatrix.sync.aligned.m8n8.x4.trans.shared.b16 {%0,%1,%2,%3}, [%4];"
        : "=r"(r[0]), "=r"(r[1]), "=r"(r[2]), "=r"(r[3]) : "r"(a));
}
__device__ __forceinline__ void mma_bf16(float c[4], const unsigned a[4], const unsigned b[2]) {
    asm volatile("mma.sync.aligned.m16n8k16.row.col.f32.bf16.bf16.f32 "
        "{%0,%1,%2,%3}, {%4,%5,%6,%7}, {%8,%9}, {%0,%1,%2,%3};"
        : "+f"(c[0]), "+f"(c[1]), "+f"(c[2]), "+f"(c[3])
        : "r"(a[0]), "r"(a[1]), "r"(a[2]), "r"(a[3]), "r"(b[0]), "r"(b[1]));
}
__device__ __forceinline__ void cpa16(unsigned dst, const void* src) {
    asm volatile("cp.async.cg.shared.global [%0], [%1], 16;" :: "r"(dst), "l"(src));
}
#define CPA_COMMIT() asm volatile("cp.async.commit_group;" ::: "memory")
#define CPA_WAIT(n)  asm volatile("cp.async.wait_group %0;" :: "n"(n) : "memory")
#define SWZ(o) ((o) ^ (((o) >> 3) & 0x70))

// fp32 W [o][i] 64x64 -> bf16 swizzled rows of 128B
__device__ __forceinline__ void w_to_smem(const float* __restrict__ w, char* dst, int t)
{
    int o = t >> 2, seg = t & 3;
    const float* ws = w + o * 64 + seg * 16;
    float f[16];
    #pragma unroll
    for (int j = 0; j < 4; j++) *(float4*)&f[j * 4] = *(const float4*)(ws + j * 4);
    unsigned u[8];
    #pragma unroll
    for (int j = 0; j < 8; j++) {
        __nv_bfloat162 h2 = __floats2bfloat162_rn(f[2 * j], f[2 * j + 1]);
        u[j] = *(unsigned*)&h2;
    }
    *(uint4*)(dst + SWZ(o * 128 + seg * 32))      = make_uint4(u[0], u[1], u[2], u[3]);
    *(uint4*)(dst + SWZ(o * 128 + seg * 32 + 16)) = make_uint4(u[4], u[5], u[6], u[7]);
}

// =====================================================================
// K1H: conv1x1 via HMMA, reading fp32 x directly.
//   fp32 x tile [64c][128px] -> smem, convert -> bf16 natural halves,
//   A-frags via ldsm.trans, B = W. Output bf16 g_T natural.
// =====================================================================
#define K1_F32  0        // 64 x 128 fp32 = 32768
#define K1_A    32768    // 2 halves x [64c][64px] bf16 = 16384
#define K1_W    49152    // 8192
#define K1_BIAS 57344    // 256
#define K1_TOT  57600

extern "C" __global__ void __launch_bounds__(256)
k1h(const float* __restrict__ xl, const float* __restrict__ xr, Ptrs4 w1, Ptrs4 b1)
{
    extern __shared__ char smc[];
    const unsigned smb = smem_u32(smc);
    const int t = threadIdx.x, wid = t >> 5, lane = t & 31;
    const int tile = blockIdx.x, b = blockIdx.y, p = blockIdx.z;
    const int px0 = tile * 128;
    const float* __restrict__ x = (p & 1) ? xr : xl;

    // stage fp32 tile
    #pragma unroll
    for (int rep = 0; rep < 8; rep++) {
        int i = t + rep * 256;
        int c = i >> 5, seg = i & 31;
        cpa16(smb + K1_F32 + c * 512 + seg * 16,
              x + ((long)(b * 64 + c)) * HW + px0 + seg * 4);
    }
    CPA_COMMIT();
    w_to_smem(w1.p[p], smc + K1_W, t);
    if (t < 64) ((float*)(smc + K1_BIAS))[t] = b1.p[p][t];
    CPA_WAIT(0);
    __syncthreads();

    // convert fp32 -> bf16 natural halves [64c][64px] swizzled
    {
        int c = t >> 2, q = t & 3;
        const float* src = (const float*)(smc + K1_F32) + c * 128 + q * 32;
        #pragma unroll
        for (int j = 0; j < 4; j++) {
            float4 f0 = *(const float4*)(src + j * 8);
            float4 f1 = *(const float4*)(src + j * 8 + 4);
            __nv_bfloat162 h0 = __floats2bfloat162_rn(f0.x, f0.y);
            __nv_bfloat162 h1 = __floats2bfloat162_rn(f0.z, f0.w);
            __nv_bfloat162 h2 = __floats2bfloat162_rn(f1.x, f1.y);
            __nv_bfloat162 h3 = __floats2bfloat162_rn(f1.z, f1.w);
            int px = q * 32 + j * 8;
            int half = px >> 6;
            *(uint4*)(smc + K1_A + half * 8192 + SWZ(c * 128 + (px & 63) * 2)) =
                make_uint4(*(unsigned*)&h0, *(unsigned*)&h1, *(unsigned*)&h2, *(unsigned*)&h3);
        }
    }
    __syncthreads();

    // A frags via trans from [k=c][m=px] storage
    unsigned afr[4][4];
    {
        int half = wid >> 2, m0l = (wid & 3) * 16;
        int akrow = (lane & 7) + ((lane >> 4) & 1) * 8;
        int amcol = ((lane >> 3) & 1) * 8;
        #pragma unroll
        for (int kb = 0; kb < 4; kb++)
            ldsm4t(smb + K1_A + half * 8192 + SWZ((kb * 16 + akrow) * 128 + (m0l + amcol) * 2),
                   afr[kb]);
    }

    const int bn = (lane & 7) + ((lane >> 4) << 3);
    const int bk = ((lane >> 3) & 1) * 16;
    float cf[8][4];
    #pragma unroll
    for (int nt = 0; nt < 8; nt++)
        #pragma unroll
        for (int q = 0; q < 4; q++) cf[nt][q] = 0.f;

    #pragma unroll
    for (int kb = 0; kb < 4; kb++) {
        #pragma unroll
        for (int ntp = 0; ntp < 4; ntp++) {
            unsigned bfr[4];
            ldsm4(smb + K1_W + SWZ((ntp * 16 + bn) * 128 + kb * 32 + bk), bfr);
            mma_bf16(cf[2 * ntp],     afr[kb], bfr);
            mma_bf16(cf[2 * ntp + 1], afr[kb], bfr + 2);
        }
    }

    __syncthreads();                      // stage region overlays K1_F32
    __nv_bfloat16* TS = (__nv_bfloat16*)smc;      // [64 o][136 px]
    const float* bias = (const float*)(smc + K1_BIAS);
    {
        int r0 = wid * 16 + (lane >> 2);
        #pragma unroll
        for (int nt = 0; nt < 8; nt++) {
            int c = nt * 8 + (lane & 3) * 2;
            float b0 = bias[c], b1v = bias[c + 1];
            TS[c * 136 + r0]           = __float2bfloat16_rn(cf[nt][0] + b0);
            TS[(c + 1) * 136 + r0]     = __float2bfloat16_rn(cf[nt][1] + b1v);
            TS[c * 136 + r0 + 8]       = __float2bfloat16_rn(cf[nt][2] + b0);
            TS[(c + 1) * 136 + r0 + 8] = __float2bfloat16_rn(cf[nt][3] + b1v);
        }
    }
    __syncthreads();

    __nv_bfloat16* To = g_T + (((long)p * BB + b) * 64) * HW + px0;
    #pragma unroll
    for (int rep = 0; rep < 4; rep++) {
        int idx = t + rep * 256;
        int row = idx >> 4, seg = idx & 15;
        *(uint4*)(To + (long)row * HW + seg * 8) = *(uint4*)&TS[row * 136 + seg * 8];
    }
}

// =====================================================================
// K2: depthwise 3x3 on bf16 T -> bf16 natural g_Qn (fp32 accumulate)
// =====================================================================
__device__ __forceinline__ void dwrow_bf(const __nv_bfloat16* __restrict__ row, int w0,
                                         float ka, float kb, float kc, float acc[4])
{
    const __nv_bfloat162* r2 = (const __nv_bfloat162*)(row + w0);
    float2 a01 = __bfloat1622float2(r2[0]);
    float2 a23 = __bfloat1622float2(r2[1]);
    float l = (w0 > 0)   ? __bfloat162float(row[w0 - 1]) : 0.f;
    float r = (w0 < 508) ? __bfloat162float(row[w0 + 4]) : 0.f;
    float col[6] = {l, a01.x, a01.y, a23.x, a23.y, r};
    #pragma unroll
    for (int k = 0; k < 4; k++)
        acc[k] += col[k] * ka + col[k + 1] * kb + col[k + 2] * kc;
}

extern "C" __global__ void __launch_bounds__(256)
k2_dwconv(Ptrs4 wd, Ptrs4 bd)
{
    long tid = (long)blockIdx.x * 256 + threadIdx.x;
    int w0 = (int)(tid & 127) * 4;
    int h  = (int)(tid >> 7) & 127;
    int c  = (int)(tid >> 14) & 63;
    int b  = (int)(tid >> 20) & 1;
    int p  = (int)(tid >> 21);

    const float* __restrict__ W = wd.p[p] + c * 9;
    float k00 = W[0], k01 = W[1], k02 = W[2];
    float k10 = W[3], k11 = W[4], k12 = W[5];
    float k20 = W[6], k21 = W[7], k22 = W[8];

    const __nv_bfloat16* __restrict__ src =
        g_T + (((long)p * BB + b) * 64 + c) * HW + (long)h * WW;
    float acc[4] = {0.f, 0.f, 0.f, 0.f};
    if (h > 0)   dwrow_bf(src - WW, w0, k00, k01, k02, acc);
    dwrow_bf(src, w0, k10, k11, k12, acc);
    if (h < 127) dwrow_bf(src + WW, w0, k20, k21, k22, acc);

    float bv = bd.p[p][c];
    __nv_bfloat162 v01 = __floats2bfloat162_rn(acc[0] + bv, acc[1] + bv);
    __nv_bfloat162 v23 = __floats2bfloat162_rn(acc[2] + bv, acc[3] + bv);
    uint2 o;
    o.x = *(unsigned*)&v01; o.y = *(unsigned*)&v23;
    *(uint2*)(g_Qn + (((long)p * BB + b) * 64 + c) * HW + (long)h * WW + w0) = o;
}

// =====================================================================
// KATT: all operands from NATURAL layout via ldsm(.trans).
//   A: Qa [64c][128w] as 2 halves; B: Qb chunk [64c][64v]; V chunk [64c][64v]
//   smem: A 16K | Bbuf 2x8K | Vbuf 2x8K = 48K -> 2 CTAs/SM
// =====================================================================
#define SM_A   0
#define SM_B   16384
#define SM_V   32768
#define SM_TOT 49152

extern "C" __global__ void __launch_bounds__(256, 2)
katt()
{
    extern __shared__ char smc[];
    const unsigned smb = smem_u32(smc);
    const int t = threadIdx.x, wid = t >> 5, lane = t & 31;
    const int wt = blockIdx.x, h = blockIdx.y;
    const int b = blockIdx.z & 1, dir = blockIdx.z >> 1;
    const int m0g = wt * 128;

    const int pa = dir ? 1 : 0, pb = dir ? 0 : 1, pv = dir ? 2 : 3;
    const __nv_bfloat16* QnA = g_Qn + ((long)(pa * BB + b) * 64) * HW + (long)h * WW;
    const __nv_bfloat16* QnB = g_Qn + ((long)(pb * BB + b) * 64) * HW + (long)h * WW;
    const __nv_bfloat16* Vn  = g_Qn + ((long)(pv * BB + b) * 64) * HW + (long)h * WW;

    auto load_chunk = [&](int ck, int buf) {
        #pragma unroll
        for (int rep = 0; rep < 2; rep++) {
            int i = t + rep * 256;
            int c = i >> 3, seg = i & 7;
            cpa16(smb + SM_B + buf * 8192 + SWZ(c * 128 + seg * 16),
                  QnB + (long)c * HW + ck * 64 + seg * 8);
        }
        #pragma unroll
        for (int rep = 0; rep < 2; rep++) {
            int i = t + rep * 256;
            int c = i >> 3, seg = i & 7;
            cpa16(smb + SM_V + buf * 8192 + SWZ(c * 128 + seg * 16),
                  Vn + (long)c * HW + ck * 64 + seg * 8);
        }
    };

    // A prologue: two [64c][64w] halves from natural layout
    #pragma unroll
    for (int rep = 0; rep < 4; rep++) {
        int i = t + rep * 256;
        int half = i >> 9, c = (i >> 3) & 63, seg = i & 7;
        cpa16(smb + SM_A + half * 8192 + SWZ(c * 128 + seg * 16),
              QnA + (long)c * HW + m0g + half * 64 + seg * 8);
    }
    load_chunk(0, 0);
    CPA_COMMIT();
    load_chunk(1, 1);
    CPA_COMMIT();
    CPA_WAIT(1);
    __syncthreads();

    // A frags via trans from [k=c][m=w] storage
    unsigned afr[4][4];
    {
        int half = wid >> 2, m0l = (wid & 3) * 16;
        int akrow = (lane & 7) + ((lane >> 4) & 1) * 8;
        int amcol = ((lane >> 3) & 1) * 8;
        #pragma unroll
        for (int kb = 0; kb < 4; kb++)
            ldsm4t(smb + SM_A + half * 8192 + SWZ((kb * 16 + akrow) * 128 + (m0l + amcol) * 2),
                   afr[kb]);
    }

    float fac[8][4];
    #pragma unroll
    for (int nt = 0; nt < 8; nt++)
        #pragma unroll
        for (int q = 0; q < 4; q++) fac[nt][q] = 0.f;
    float rs0 = 0.f, rs1 = 0.f;

    const int bn = (lane & 7) + ((lane >> 4) << 3);   // GEMM2 (non-trans)
    const int bk = ((lane >> 3) & 1) * 16;
    const int tkrow = lane & 15;                      // GEMM1 B (trans)
    const int tncol = (lane >> 4) * 8;

    for (int ck = 0; ck < 8; ck++) {
        const int buf = ck & 1;
        float cf[8][4];
        #pragma unroll
        for (int nt = 0; nt < 8; nt++)
            #pragma unroll
            for (int q = 0; q < 4; q++) cf[nt][q] = 0.f;

        // GEMM1: B frags via trans from [k=c][n=v] storage
        unsigned b1base = smb + SM_B + buf * 8192;
        #pragma unroll
        for (int kb = 0; kb < 4; kb++) {
            #pragma unroll
            for (int ntp = 0; ntp < 4; ntp++) {
                unsigned bfr[4];
                ldsm4t(b1base + SWZ((kb * 16 + tkrow) * 128 + (ntp * 16 + tncol) * 2), bfr);
                mma_bf16(cf[2 * ntp],     afr[kb], bfr);
                mma_bf16(cf[2 * ntp + 1], afr[kb], bfr + 2);
            }
        }

        // exp + rowsum + repack C-frags as A-frags
        unsigned pfr[4][4];
        #pragma unroll
        for (int nt = 0; nt < 8; nt++) {
            float e0 = __expf(cf[nt][0] * ATT_SCALE);
            float e1 = __expf(cf[nt][1] * ATT_SCALE);
            float e2 = __expf(cf[nt][2] * ATT_SCALE);
            float e3 = __expf(cf[nt][3] * ATT_SCALE);
            rs0 += e0 + e1; rs1 += e2 + e3;
            __nv_bfloat162 p01 = __floats2bfloat162_rn(e0, e1);
            __nv_bfloat162 p23 = __floats2bfloat162_rn(e2, e3);
            pfr[nt >> 1][(nt & 1) * 2 + 0] = *(unsigned*)&p01;
            pfr[nt >> 1][(nt & 1) * 2 + 1] = *(unsigned*)&p23;
        }

        // GEMM2: B = V tile [n=c][k=v] (non-trans)
        unsigned vbase = smb + SM_V + buf * 8192;
        #pragma unroll
        for (int kb = 0; kb < 4; kb++) {
            #pragma unroll
            for (int ntp = 0; ntp < 4; ntp++) {
                unsigned bfr[4];
                ldsm4(vbase + SWZ((ntp * 16 + bn) * 128 + kb * 32 + bk), bfr);
                mma_bf16(fac[2 * ntp],     pfr[kb], bfr);
                mma_bf16(fac[2 * ntp + 1], pfr[kb], bfr + 2);
            }
        }

        if (ck < 7) {
            __syncthreads();
            if (ck + 2 < 8) {
                load_chunk(ck + 2, buf);
                CPA_COMMIT();
                CPA_WAIT(1);
            } else {
                CPA_WAIT(0);
            }
            __syncthreads();
        }
    }

    rs0 += __shfl_xor_sync(0xffffffffu, rs0, 1);
    rs0 += __shfl_xor_sync(0xffffffffu, rs0, 2);
    rs1 += __shfl_xor_sync(0xffffffffu, rs1, 1);
    rs1 += __shfl_xor_sync(0xffffffffu, rs1, 2);
    float inv0 = 1.f / rs0, inv1 = 1.f / rs1;

    __syncthreads();                      // smem dead -> F staging
    __nv_bfloat16* FSh = (__nv_bfloat16*)smc;     // [128 px][72 c]
    {
        int r0 = wid * 16 + (lane >> 2);
        #pragma unroll
        for (int nt = 0; nt < 8; nt++) {
            int c = nt * 8 + (lane & 3) * 2;
            __nv_bfloat162 p0 = __floats2bfloat162_rn(fac[nt][0] * inv0, fac[nt][1] * inv0);
            __nv_bfloat162 p1 = __floats2bfloat162_rn(fac[nt][2] * inv1, fac[nt][3] * inv1);
            *(__nv_bfloat162*)&FSh[r0 * 72 + c]       = p0;
            *(__nv_bfloat162*)&FSh[(r0 + 8) * 72 + c] = p1;
        }
    }
    __syncthreads();

    __nv_bfloat16* FoT = g_FT + (long)dir * PLANE
                         + ((long)b * HW + (long)h * WW + m0g) * 64;
    #pragma unroll
    for (int rep = 0; rep < 4; rep++) {
        int idx = t + rep * 256;
        int px = idx >> 3, seg = idx & 7;
        *(uint4*)(FoT + (long)px * 64 + seg * 8) = *(uint4*)&FSh[px * 72 + seg * 8];
    }
}

// =====================================================================
// K5H: out = x_l + x_r + conv1x1(F0,lp3) + conv1x1(F1,rp3) via HMMA
// =====================================================================
#define K5_A0  0
#define K5_A1  16384
#define K5_W   32768
#define K5_BS  49152
#define K5_TOT 49408

extern "C" __global__ void __launch_bounds__(256)
k5h(const float* __restrict__ xl, const float* __restrict__ xr,
    const float* __restrict__ wl3, const float* __restrict__ bl3,
    const float* __restrict__ wr3, const float* __restrict__ br3,
    float* __restrict__ out)
{
    extern __shared__ char smc[];
    const unsigned smb = smem_u32(smc);
    const int t = threadIdx.x, wid = t >> 5, lane = t & 31;
    const int tile = blockIdx.x, b = blockIdx.y;
    const int px0 = tile * 128;

    #pragma unroll
    for (int d = 0; d < 2; d++) {
        const __nv_bfloat16* FT = g_FT + (long)d * PLANE + ((long)b * HW + px0) * 64;
        #pragma unroll
        for (int rep = 0; rep < 4; rep++) {
            int i = t + rep * 256;
            int r = i >> 3, ch = i & 7;
            cpa16(smb + K5_A0 + d * 16384 + SWZ(r * 128 + ch * 16), FT + (long)r * 64 + ch * 8);
        }
    }
    CPA_COMMIT();
    w_to_smem(wl3, smc + K5_W, t);
    w_to_smem(wr3, smc + K5_W + 8192, t);
    if (t < 64) ((float*)(smc + K5_BS))[t] = bl3[t] + br3[t];
    CPA_WAIT(0);
    __syncthreads();

    unsigned afr0[4][4], afr1[4][4];
    {
        int row = wid * 16 + (lane & 15);
        int chalf = (lane >> 4) * 16;
        #pragma unroll
        for (int kb = 0; kb < 4; kb++) {
            ldsm4(smb + K5_A0 + SWZ(row * 128 + kb * 32 + chalf), afr0[kb]);
            ldsm4(smb + K5_A1 + SWZ(row * 128 + kb * 32 + chalf), afr1[kb]);
        }
    }

    const int bn = (lane & 7) + ((lane >> 4) << 3);
    const int bk = ((lane >> 3) & 1) * 16;
    float cf[8][4];
    #pragma unroll
    for (int nt = 0; nt < 8; nt++)
        #pragma unroll
        for (int q = 0; q < 4; q++) cf[nt][q] = 0.f;

    #pragma unroll
    for (int kb = 0; kb < 4; kb++) {
        #pragma unroll
        for (int ntp = 0; ntp < 4; ntp++) {
            unsigned bfr[4];
            ldsm4(smb + K5_W + SWZ((ntp * 16 + bn) * 128 + kb * 32 + bk), bfr);
            mma_bf16(cf[2 * ntp],     afr0[kb], bfr);
            mma_bf16(cf[2 * ntp + 1], afr0[kb], bfr + 2);
            ldsm4(smb + K5_W + 8192 + SWZ((ntp * 16 + bn) * 128 + kb * 32 + bk), bfr);
            mma_bf16(cf[2 * ntp],     afr1[kb], bfr);
            mma_bf16(cf[2 * ntp + 1], afr1[kb], bfr + 2);
        }
    }

    __syncthreads();                      // stage fp32 [64 o][136 px]
    float* TS = (float*)smc;
    const float* bias = (const float*)(smc + K5_BS);
    {
        int r0 = wid * 16 + (lane >> 2);
        #pragma unroll
        for (int nt = 0; nt < 8; nt++) {
            int c = nt * 8 + (lane & 3) * 2;
            float b0 = bias[c], b1v = bias[c + 1];
            TS[c * 136 + r0]           = cf[nt][0] + b0;
            TS[(c + 1) * 136 + r0]     = cf[nt][1] + b1v;
            TS[c * 136 + r0 + 8]       = cf[nt][2] + b0;
            TS[(c + 1) * 136 + r0 + 8] = cf[nt][3] + b1v;
        }
    }
    __syncthreads();

    #pragma unroll
    for (int rep = 0; rep < 8; rep++) {
        int idx = t + rep * 256;
        int row = idx >> 5, seg = (idx & 31) * 4;
        float4 v = *(float4*)&TS[row * 136 + seg];
        long ob = ((long)b * 64 + row) * HW + px0 + seg;
        float4 a = *(const float4*)(xl + ob);
        float4 c = *(const float4*)(xr + ob);
        v.x += a.x + c.x; v.y += a.y + c.y;
        v.z += a.z + c.z; v.w += a.w + c.w;
        *(float4*)(out + ob) = v;
    }
}

// =====================================================================
extern "C" void kernel_launch(void* const* d_in, const int* in_sizes, int n_in,
                              void* d_out, int out_size)
{
    const float* xl = (const float*)d_in[0];
    const float* xr = (const float*)d_in[1];
    Ptrs4 w1 = {{(const float*)d_in[2],  (const float*)d_in[6],
                 (const float*)d_in[10], (const float*)d_in[14]}};
    Ptrs4 b1 = {{(const float*)d_in[3],  (const float*)d_in[7],
                 (const float*)d_in[11], (const float*)d_in[15]}};
    Ptrs4 wd = {{(const float*)d_in[4],  (const float*)d_in[8],
                 (const float*)d_in[12], (const float*)d_in[16]}};
    Ptrs4 bd = {{(const float*)d_in[5],  (const float*)d_in[9],
                 (const float*)d_in[13], (const float*)d_in[17]}};
    const float* wl3 = (const float*)d_in[18];
    const float* bl3 = (const float*)d_in[19];
    const float* wr3 = (const float*)d_in[20];
    const float* br3 = (const float*)d_in[21];

    cudaFuncSetAttribute(k1h,  cudaFuncAttributeMaxDynamicSharedMemorySize, K1_TOT);
    cudaFuncSetAttribute(katt, cudaFuncAttributeMaxDynamicSharedMemorySize, SM_TOT);
    cudaFuncSetAttribute(k5h,  cudaFuncAttributeMaxDynamicSharedMemorySize, K5_TOT);

    k1h<<<dim3(512, 2, 4), 256, K1_TOT>>>(xl, xr, w1, b1);
    k2_dwconv<<<32768, 256>>>(wd, bd);
    katt<<<dim3(4, 128, 4), 256, SM_TOT>>>();
    k5h<<<dim3(512, 2), 256, K5_TOT>>>(xl, xr, wl3, bl3, wr3, br3, (float*)d_out);
}